// round 4
// baseline (speedup 1.0000x reference)
#include <cuda_runtime.h>
#include <cuda_bf16.h>
#include <cstdint>
#include <cstddef>

// Problem constants
#define SEQ   2048
#define BATCH 16
#define HID   512
#define OUT_F 10
#define NLAY  5
#define MROWS (SEQ * BATCH)      // 32768
#define NCOLS (3 * HID)          // 1536
#define BH    (BATCH * HID)      // 8192

// -------- device scratch (no allocations allowed) --------
__device__ float g_U [(size_t)MROWS * NCOLS];   // 192 MB: per-layer [xt | f | r]
__device__ float g_h0[(size_t)MROWS * HID];     // 64 MB ping
__device__ float g_h1[(size_t)MROWS * HID];     // 64 MB pong
__device__ float g_Wt[(size_t)HID * NCOLS];     // 3 MB: W transposed to [K, N]

// ============================================================
// Transpose W [1536, 512] -> Wt [512, 1536]
// ============================================================
__global__ void transposeW(const float* __restrict__ W, float* __restrict__ Wt) {
    __shared__ float t[32][33];
    int bx = blockIdx.x * 32;   // over K=512
    int by = blockIdx.y * 32;   // over G=1536
    int x = threadIdx.x, y = threadIdx.y;   // 32 x 8
#pragma unroll
    for (int i = 0; i < 32; i += 8)
        t[y + i][x] = W[(size_t)(by + y + i) * HID + bx + x];
    __syncthreads();
#pragma unroll
    for (int i = 0; i < 32; i += 8)
        Wt[(size_t)(bx + y + i) * NCOLS + by + x] = t[x][y + i];
}

// ============================================================
// Fused SGEMM: U[m,n] = sum_k A[m,k] * Wt[k,n]; epilogue:
//   n <  512        : store xt
//   512 <= n < 1536 : store sigmoid(u + bias[n-512])   (f then r)
// M=32768, N=1536, K=512.  128x128x16 tile, 256 threads, 8x8/thread.
// ============================================================
#define BM 128
#define BN 128
#define BKK 16
#define TM 8
#define TN 8

__global__ void __launch_bounds__(256)
sru_gemm_fused(const float* __restrict__ A, const float* __restrict__ Bt,
               const float* __restrict__ bias, float* __restrict__ U) {
    __shared__ float As[BKK][BM];
    __shared__ float Bs[BKK][BN];

    const int tid = threadIdx.x;
    const int bm = blockIdx.y * BM;
    const int bn = blockIdx.x * BN;
    const int tx = tid & 15;        // 0..15
    const int ty = tid >> 4;        // 0..15

    float acc[TM][TN];
#pragma unroll
    for (int i = 0; i < TM; i++)
#pragma unroll
        for (int j = 0; j < TN; j++) acc[i][j] = 0.f;

    for (int k0 = 0; k0 < HID; k0 += BKK) {
        // ---- load A tile [128 x 16] (transposed into As[k][m]) ----
#pragma unroll
        for (int i = 0; i < 2; i++) {
            int idx = tid + i * 256;              // 0..511
            int row = idx >> 2;                   // 0..127
            int col = (idx & 3) << 2;             // 0,4,8,12
            float4 v = *reinterpret_cast<const float4*>(
                &A[(size_t)(bm + row) * HID + k0 + col]);
            As[col + 0][row] = v.x;
            As[col + 1][row] = v.y;
            As[col + 2][row] = v.z;
            As[col + 3][row] = v.w;
        }
        // ---- load B tile [16 x 128] ----
#pragma unroll
        for (int i = 0; i < 2; i++) {
            int idx = tid + i * 256;
            int row = idx >> 5;                   // 0..15
            int col = (idx & 31) << 2;            // 0..124
            *reinterpret_cast<float4*>(&Bs[row][col]) =
                *reinterpret_cast<const float4*>(
                    &Bt[(size_t)(k0 + row) * NCOLS + bn + col]);
        }
        __syncthreads();

#pragma unroll
        for (int kk = 0; kk < BKK; kk++) {
            float a[TM], b[TN];
#pragma unroll
            for (int i = 0; i < TM; i++) a[i] = As[kk][ty * TM + i];
#pragma unroll
            for (int j = 0; j < TN; j++) b[j] = Bs[kk][tx * TN + j];
#pragma unroll
            for (int i = 0; i < TM; i++)
#pragma unroll
                for (int j = 0; j < TN; j++)
                    acc[i][j] = fmaf(a[i], b[j], acc[i][j]);
        }
        __syncthreads();
    }

    // ---- epilogue: bias + sigmoid on gate columns, vectorized stores ----
    const bool gate = (bn >= HID);   // whole block column is one region (HID % BN == 0)
#pragma unroll
    for (int i = 0; i < TM; i++) {
        int m = bm + ty * TM + i;
        float* urow = &U[(size_t)m * NCOLS + bn + tx * TN];
#pragma unroll
        for (int jj = 0; jj < TN; jj += 4) {
            float4 v;
            float* pv = &v.x;
#pragma unroll
            for (int q = 0; q < 4; q++) {
                float u = acc[i][jj + q];
                if (gate) {
                    int n = bn + tx * TN + jj + q;
                    u += bias[n - HID];
                    u = 1.0f / (1.0f + expf(-u));
                }
                pv[q] = u;
            }
            *reinterpret_cast<float4*>(urow + jj) = v;
        }
    }
}

// ============================================================
// SRU scan + highway: one thread per (b,h) lane, serial over L.
//   c_t = f*c_{t-1} + (1-f)*xt ;  h = r*c + (1-r)*x
// Unroll-8 with front-batched loads for MLP.
// ============================================================
#define SUNROLL 8

__global__ void sru_scan(const float* __restrict__ U, const float* __restrict__ xin,
                         float* __restrict__ hout) {
    int gid = blockIdx.x * blockDim.x + threadIdx.x;   // 0..8191
    int b = gid >> 9;          // 0..15
    int h = gid & (HID - 1);   // 0..511

    float c = 0.f;
    for (int l = 0; l < SEQ; l += SUNROLL) {
        float xt[SUNROLL], f[SUNROLL], r[SUNROLL], xv[SUNROLL];
#pragma unroll
        for (int u = 0; u < SUNROLL; u++) {
            size_t row = (size_t)(l + u) * BATCH + b;
            const float* up = U + row * NCOLS + h;
            xt[u] = up[0];
            f [u] = up[HID];
            r [u] = up[2 * HID];
            xv[u] = xin[row * HID + h];
        }
#pragma unroll
        for (int u = 0; u < SUNROLL; u++) {
            c = fmaf(f[u], c - xt[u], xt[u]);          // f*c + (1-f)*xt
            float hv = fmaf(r[u], c - xv[u], xv[u]);   // r*c + (1-r)*x
            size_t row = (size_t)(l + u) * BATCH + b;
            hout[row * HID + h] = hv;
        }
    }
}

// ============================================================
// Final FC: out[m, n] = sum_k H[m,k]*fcW[n,k] + fcb[n]
// One warp per row; fc_W staged in smem.
// ============================================================
__global__ void __launch_bounds__(256)
fc_kernel(const float* __restrict__ Hf, const float* __restrict__ fcW,
          const float* __restrict__ fcb, float* __restrict__ out) {
    __shared__ float Wsm[OUT_F * HID];   // 20 KB
    int tid = threadIdx.x;
    for (int i = tid; i < OUT_F * HID; i += 256) Wsm[i] = fcW[i];
    __syncthreads();

    int warp = tid >> 5, lane = tid & 31;
    int row = blockIdx.x * 8 + warp;
    const float* hp = Hf + (size_t)row * HID;

    float acc[OUT_F];
#pragma unroll
    for (int n = 0; n < OUT_F; n++) acc[n] = 0.f;

    for (int k = lane; k < HID; k += 32) {
        float xv = hp[k];
#pragma unroll
        for (int n = 0; n < OUT_F; n++)
            acc[n] = fmaf(xv, Wsm[n * HID + k], acc[n]);
    }
#pragma unroll
    for (int n = 0; n < OUT_F; n++) {
        float v = acc[n];
        v += __shfl_xor_sync(0xFFFFFFFFu, v, 16);
        v += __shfl_xor_sync(0xFFFFFFFFu, v, 8);
        v += __shfl_xor_sync(0xFFFFFFFFu, v, 4);
        v += __shfl_xor_sync(0xFFFFFFFFu, v, 2);
        v += __shfl_xor_sync(0xFFFFFFFFu, v, 1);
        if (lane == 0) out[(size_t)row * OUT_F + n] = v + fcb[n];
    }
}

// ============================================================
// Host launcher (graph-capturable: kernel launches only)
// ============================================================
extern "C" void kernel_launch(void* const* d_in, const int* in_sizes, int n_in,
                              void* d_out, int out_size) {
    const float* x    = (const float*)d_in[0];   // [2048,16,512]
    const float* Ws   = (const float*)d_in[1];   // [5,1536,512]
    const float* bs   = (const float*)d_in[2];   // [5,1024]
    const float* fcW  = (const float*)d_in[3];   // [10,512]
    const float* fcb  = (const float*)d_in[4];   // [10]
    float* out        = (float*)d_out;           // [2048,16,10]

    float *U, *h0, *h1, *Wt;
    cudaGetSymbolAddress((void**)&U,  g_U);
    cudaGetSymbolAddress((void**)&h0, g_h0);
    cudaGetSymbolAddress((void**)&h1, g_h1);
    cudaGetSymbolAddress((void**)&Wt, g_Wt);

    dim3 tW_grid(HID / 32, NCOLS / 32), tW_blk(32, 8);
    dim3 gm_grid(NCOLS / BN, MROWS / BM);

    const float* cur = x;
    for (int l = 0; l < NLAY; l++) {
        transposeW<<<tW_grid, tW_blk>>>(Ws + (size_t)l * NCOLS * HID, Wt);
        sru_gemm_fused<<<gm_grid, 256>>>(cur, Wt, bs + (size_t)l * (2 * HID), U);
        float* hout = (l & 1) ? h1 : h0;
        sru_scan<<<BH / 32, 32>>>(U, cur, hout);
        cur = hout;
    }
    fc_kernel<<<MROWS / 8, 256>>>(cur, fcW, fcb, out);
}

// round 6
// speedup vs baseline: 1.6138x; 1.6138x over previous
#include <cuda_runtime.h>
#include <cuda_bf16.h>
#include <cstdint>
#include <cstddef>

// Problem constants
#define SEQ   2048
#define BATCH 16
#define HID   512
#define OUT_F 10
#define NLAY  5
#define MROWS (SEQ * BATCH)      // 32768
#define NCOLS (3 * HID)          // 1536
#define BH    (BATCH * HID)      // 8192

// ---------------- device scratch (no allocations allowed) ----------------
__device__ float g_U [(size_t)MROWS * NCOLS];          // 192 MB: [xt | f | r]
__device__ float g_h0[(size_t)MROWS * HID];            // 64 MB ping
__device__ float g_h1[(size_t)MROWS * HID];            // 64 MB pong
__device__ __nv_bfloat16 g_Ahi[(size_t)MROWS * HID];   // 32 MB
__device__ __nv_bfloat16 g_Alo[(size_t)MROWS * HID];   // 32 MB
__device__ __nv_bfloat16 g_Whi[(size_t)NCOLS * HID];   // 1.5 MB
__device__ __nv_bfloat16 g_Wlo[(size_t)NCOLS * HID];   // 1.5 MB

// ================= arch-neutral PTX helpers (sm_80+ features only) =======
__device__ __forceinline__ uint32_t smem_to_u32(const void* p) {
    uint32_t a;
    asm("{ .reg .u64 t; cvta.to.shared.u64 t, %1; cvt.u32.u64 %0, t; }"
        : "=r"(a) : "l"(p));
    return a;
}

__device__ __forceinline__ void cp16(uint32_t saddr, const void* g) {
    asm volatile("cp.async.cg.shared.global [%0], [%1], 16;"
                 :: "r"(saddr), "l"(g) : "memory");
}
__device__ __forceinline__ void cp_commit() {
    asm volatile("cp.async.commit_group;" ::: "memory");
}
template <int N>
__device__ __forceinline__ void cp_wait() {
    asm volatile("cp.async.wait_group %0;" :: "n"(N) : "memory");
}

__device__ __forceinline__ void ldsm_x4(uint32_t (&r)[4], uint32_t addr) {
    asm volatile("ldmatrix.sync.aligned.m8n8.x4.shared.b16 {%0,%1,%2,%3}, [%4];"
                 : "=r"(r[0]), "=r"(r[1]), "=r"(r[2]), "=r"(r[3])
                 : "r"(addr));
}
__device__ __forceinline__ uint32_t lds32(uint32_t addr) {
    uint32_t v;
    asm volatile("ld.shared.b32 %0, [%1];" : "=r"(v) : "r"(addr));
    return v;
}
__device__ __forceinline__ void mma_bf16(float (&d)[4], const uint32_t (&a)[4],
                                         uint32_t b0, uint32_t b1) {
    asm volatile(
        "mma.sync.aligned.m16n8k16.row.col.f32.bf16.bf16.f32 "
        "{%0,%1,%2,%3}, {%4,%5,%6,%7}, {%8,%9}, {%0,%1,%2,%3};"
        : "+f"(d[0]), "+f"(d[1]), "+f"(d[2]), "+f"(d[3])
        : "r"(a[0]), "r"(a[1]), "r"(a[2]), "r"(a[3]), "r"(b0), "r"(b1));
}

// ============================================================
// Split fp32 -> (hi, lo) bf16.  n4 = element_count / 4.
// ============================================================
__global__ void split_bf16(const float* __restrict__ in,
                           __nv_bfloat16* __restrict__ hi,
                           __nv_bfloat16* __restrict__ lo, int n4) {
    int i = blockIdx.x * blockDim.x + threadIdx.x;
    if (i >= n4) return;
    float4 v = reinterpret_cast<const float4*>(in)[i];
    const float* pv = &v.x;
    __nv_bfloat16 h[4], l[4];
#pragma unroll
    for (int j = 0; j < 4; j++) {
        h[j] = __float2bfloat16(pv[j]);
        l[j] = __float2bfloat16(pv[j] - __bfloat162float(h[j]));
    }
    reinterpret_cast<uint2*>(hi)[i] = *reinterpret_cast<uint2*>(h);
    reinterpret_cast<uint2*>(lo)[i] = *reinterpret_cast<uint2*>(l);
}

// ============================================================
// Tensor-core GEMM via mma.sync (bf16 2-term split, fp32 accum):
//   U[M=32768, N=1536] = A[M,512] * W[N,512]^T
// CTA tile 128x128, BK=64, 3-stage cp.async pipeline.
// 8 warps: warp tile 32(M) x 64(N) -> 2 x 8 fragments.
// Epilogue: cols >= 512 -> sigmoid(u + bias[n-512]).
// ============================================================
#define BK 64
#define PITCH_E 72                       // padded elems per row (144 B)
#define PITCH_B 144
#define TILE_B (128 * PITCH_B)           // 18432 B per (128 x 64 bf16) tile
#define STAGE_B (4 * TILE_B)             // Ahi|Alo|Bhi|Blo = 73728 B
#define NSTAGE 3
#define SMEM_GEMM (NSTAGE * STAGE_B)     // 221184 B

__device__ __forceinline__ void issue_stage(
    uint32_t sbase, const __nv_bfloat16* __restrict__ Ahi,
    const __nv_bfloat16* __restrict__ Alo,
    const __nv_bfloat16* __restrict__ Whi,
    const __nv_bfloat16* __restrict__ Wlo,
    int bm, int bn, int k0, int tid)
{
#pragma unroll
    for (int i = 0; i < 16; i++) {
        int c   = tid + i * 256;          // 0..4095
        int idx = c & 1023;
        int row = idx >> 3;               // 0..127
        int kc  = idx & 7;                // 16B chunk within 128B row
        uint32_t sa = sbase + (uint32_t)((i >> 2) * TILE_B)
                    + (uint32_t)(row * PITCH_B + kc * 16);
        const __nv_bfloat16* src;
        const int t = i >> 2;
        if      (t == 0) src = Ahi + (size_t)(bm + row) * HID + k0 + kc * 8;
        else if (t == 1) src = Alo + (size_t)(bm + row) * HID + k0 + kc * 8;
        else if (t == 2) src = Whi + (size_t)(bn + row) * HID + k0 + kc * 8;
        else             src = Wlo + (size_t)(bn + row) * HID + k0 + kc * 8;
        cp16(sa, src);
    }
    cp_commit();
}

__global__ void __launch_bounds__(256, 1)
sru_gemm_mma(const __nv_bfloat16* __restrict__ Ahi,
             const __nv_bfloat16* __restrict__ Alo,
             const __nv_bfloat16* __restrict__ Whi,
             const __nv_bfloat16* __restrict__ Wlo,
             const float* __restrict__ bias,
             float* __restrict__ U)
{
    extern __shared__ char smem[];
    const uint32_t sb = smem_to_u32(smem);

    const int tid    = threadIdx.x;
    const int wid    = tid >> 5;
    const int lane   = tid & 31;
    const int group  = lane >> 2;         // 0..7
    const int tid4   = lane & 3;          // 0..3
    const int m_off  = (wid & 3) * 32;
    const int n_off  = (wid >> 2) * 64;
    const int bn     = blockIdx.x * 128;
    const int bm     = blockIdx.y * 128;
    const bool gate  = (bn >= HID);

    // ldmatrix per-lane row/k offsets (A fragment, x4)
    const int lrow = (lane & 7) + ((lane >> 3) & 1) * 8;   // 0..15
    const int lkb  = ((lane >> 4) & 1) * 8;                // 0 or 8

    float acc[2][8][4];
#pragma unroll
    for (int mi = 0; mi < 2; mi++)
#pragma unroll
        for (int ni = 0; ni < 8; ni++)
#pragma unroll
            for (int q = 0; q < 4; q++) acc[mi][ni][q] = 0.f;

    // prologue: stages 0, 1
    issue_stage(sb + 0 * STAGE_B, Ahi, Alo, Whi, Wlo, bm, bn, 0,  tid);
    issue_stage(sb + 1 * STAGE_B, Ahi, Alo, Whi, Wlo, bm, bn, BK, tid);

#pragma unroll 1
    for (int s = 0; s < HID / BK; s++) {               // 8 stages
        if (s < 7) cp_wait<1>(); else cp_wait<0>();
        __syncthreads();                                // stage s visible to all

        // issue stage s+2 (buffer (s+2)%3 == (s-1)%3, fully consumed by barrier)
        if (s + 2 < HID / BK)
            issue_stage(sb + ((s + 2) % NSTAGE) * STAGE_B,
                        Ahi, Alo, Whi, Wlo, bm, bn, (s + 2) * BK, tid);

        const uint32_t st  = sb + (s % NSTAGE) * STAGE_B;
        const uint32_t sAh = st;
        const uint32_t sAl = st + TILE_B;
        const uint32_t sBh = st + 2 * TILE_B;
        const uint32_t sBl = st + 3 * TILE_B;

#pragma unroll
        for (int kk = 0; kk < BK / 16; kk++) {
            const int kbase = kk * 16;
            uint32_t a_hi[2][4], a_lo[2][4];
#pragma unroll
            for (int mi = 0; mi < 2; mi++) {
                uint32_t ao = (uint32_t)((m_off + mi * 16 + lrow) * PITCH_B
                                         + (kbase + lkb) * 2);
                ldsm_x4(a_hi[mi], sAh + ao);
                ldsm_x4(a_lo[mi], sAl + ao);
            }
            uint32_t b_hi[8][2], b_lo[8][2];
#pragma unroll
            for (int ni = 0; ni < 8; ni++) {
                uint32_t bo = (uint32_t)((n_off + ni * 8 + group) * PITCH_B
                                         + (kbase + tid4 * 2) * 2);
                b_hi[ni][0] = lds32(sBh + bo);
                b_hi[ni][1] = lds32(sBh + bo + 16);
                b_lo[ni][0] = lds32(sBl + bo);
                b_lo[ni][1] = lds32(sBl + bo + 16);
            }
#pragma unroll
            for (int mi = 0; mi < 2; mi++)
#pragma unroll
                for (int ni = 0; ni < 8; ni++) {
                    mma_bf16(acc[mi][ni], a_hi[mi], b_hi[ni][0], b_hi[ni][1]);
                    mma_bf16(acc[mi][ni], a_hi[mi], b_lo[ni][0], b_lo[ni][1]);
                    mma_bf16(acc[mi][ni], a_lo[mi], b_hi[ni][0], b_hi[ni][1]);
                }
        }
        __syncthreads();   // all warps done with buffer s%3 before next issue
    }

    // ---- epilogue: bias + sigmoid on gate cols, float2 stores ----
#pragma unroll
    for (int mi = 0; mi < 2; mi++) {
        const int row0 = bm + m_off + mi * 16 + group;
#pragma unroll
        for (int ni = 0; ni < 8; ni++) {
            const int col = bn + n_off + ni * 8 + tid4 * 2;
            float u0 = acc[mi][ni][0], u1 = acc[mi][ni][1];
            float u2 = acc[mi][ni][2], u3 = acc[mi][ni][3];
            if (gate) {
                const float bz0 = __ldg(&bias[col - HID]);
                const float bz1 = __ldg(&bias[col + 1 - HID]);
                u0 = 1.0f / (1.0f + expf(-(u0 + bz0)));
                u1 = 1.0f / (1.0f + expf(-(u1 + bz1)));
                u2 = 1.0f / (1.0f + expf(-(u2 + bz0)));
                u3 = 1.0f / (1.0f + expf(-(u3 + bz1)));
            }
            *reinterpret_cast<float2*>(&U[(size_t)row0 * NCOLS + col]) =
                make_float2(u0, u1);
            *reinterpret_cast<float2*>(&U[(size_t)(row0 + 8) * NCOLS + col]) =
                make_float2(u2, u3);
        }
    }
}

// ============================================================
// SRU scan + highway (known-good)
// ============================================================
#define SUNROLL 8
__global__ void sru_scan(const float* __restrict__ U, const float* __restrict__ xin,
                         float* __restrict__ hout) {
    int gid = blockIdx.x * blockDim.x + threadIdx.x;   // 0..8191
    int b = gid >> 9;
    int h = gid & (HID - 1);

    float c = 0.f;
    for (int l = 0; l < SEQ; l += SUNROLL) {
        float xt[SUNROLL], f[SUNROLL], r[SUNROLL], xv[SUNROLL];
#pragma unroll
        for (int u = 0; u < SUNROLL; u++) {
            size_t row = (size_t)(l + u) * BATCH + b;
            const float* up = U + row * NCOLS + h;
            xt[u] = up[0];
            f [u] = up[HID];
            r [u] = up[2 * HID];
            xv[u] = xin[row * HID + h];
        }
#pragma unroll
        for (int u = 0; u < SUNROLL; u++) {
            c = fmaf(f[u], c - xt[u], xt[u]);
            float hv = fmaf(r[u], c - xv[u], xv[u]);
            size_t row = (size_t)(l + u) * BATCH + b;
            hout[row * HID + h] = hv;
        }
    }
}

// ============================================================
// Final FC (known-good)
// ============================================================
__global__ void __launch_bounds__(256)
fc_kernel(const float* __restrict__ Hf, const float* __restrict__ fcW,
          const float* __restrict__ fcb, float* __restrict__ out) {
    __shared__ float Wsm[OUT_F * HID];
    int tid = threadIdx.x;
    for (int i = tid; i < OUT_F * HID; i += 256) Wsm[i] = fcW[i];
    __syncthreads();

    int warp = tid >> 5, lane = tid & 31;
    int row = blockIdx.x * 8 + warp;
    const float* hp = Hf + (size_t)row * HID;

    float acc[OUT_F];
#pragma unroll
    for (int n = 0; n < OUT_F; n++) acc[n] = 0.f;

    for (int k = lane; k < HID; k += 32) {
        float xv = hp[k];
#pragma unroll
        for (int n = 0; n < OUT_F; n++)
            acc[n] = fmaf(xv, Wsm[n * HID + k], acc[n]);
    }
#pragma unroll
    for (int n = 0; n < OUT_F; n++) {
        float v = acc[n];
        v += __shfl_xor_sync(0xFFFFFFFFu, v, 16);
        v += __shfl_xor_sync(0xFFFFFFFFu, v, 8);
        v += __shfl_xor_sync(0xFFFFFFFFu, v, 4);
        v += __shfl_xor_sync(0xFFFFFFFFu, v, 2);
        v += __shfl_xor_sync(0xFFFFFFFFu, v, 1);
        if (lane == 0) out[(size_t)row * OUT_F + n] = v + fcb[n];
    }
}

// ============================================================
// Host launcher (graph-capturable: kernel launches only)
// ============================================================
extern "C" void kernel_launch(void* const* d_in, const int* in_sizes, int n_in,
                              void* d_out, int out_size) {
    const float* x    = (const float*)d_in[0];
    const float* Ws   = (const float*)d_in[1];
    const float* bs   = (const float*)d_in[2];
    const float* fcW  = (const float*)d_in[3];
    const float* fcb  = (const float*)d_in[4];
    float* out        = (float*)d_out;

    float *U, *h0, *h1;
    __nv_bfloat16 *Ahi, *Alo, *Whi, *Wlo;
    cudaGetSymbolAddress((void**)&U,   g_U);
    cudaGetSymbolAddress((void**)&h0,  g_h0);
    cudaGetSymbolAddress((void**)&h1,  g_h1);
    cudaGetSymbolAddress((void**)&Ahi, g_Ahi);
    cudaGetSymbolAddress((void**)&Alo, g_Alo);
    cudaGetSymbolAddress((void**)&Whi, g_Whi);
    cudaGetSymbolAddress((void**)&Wlo, g_Wlo);

    cudaFuncSetAttribute(sru_gemm_mma,
                         cudaFuncAttributeMaxDynamicSharedMemorySize, SMEM_GEMM);

    const int nA4 = MROWS * HID / 4;
    const int nW4 = NCOLS * HID / 4;
    dim3 gm_grid(NCOLS / 128, MROWS / 128);   // (12, 256)

    const float* cur = x;
    for (int l = 0; l < NLAY; l++) {
        split_bf16<<<(nA4 + 255) / 256, 256>>>(cur, Ahi, Alo, nA4);
        split_bf16<<<(nW4 + 255) / 256, 256>>>(Ws + (size_t)l * NCOLS * HID, Whi, Wlo, nW4);
        sru_gemm_mma<<<gm_grid, 256, SMEM_GEMM>>>(Ahi, Alo, Whi, Wlo,
                                                  bs + (size_t)l * (2 * HID), U);
        float* hout = (l & 1) ? h1 : h0;
        sru_scan<<<BH / 32, 32>>>(U, cur, hout);
        cur = hout;
    }
    fc_kernel<<<MROWS / 8, 256>>>(cur, fcW, fcb, out);
}

// round 7
// speedup vs baseline: 2.3420x; 1.4512x over previous
#include <cuda_runtime.h>
#include <cuda_bf16.h>
#include <cstdint>
#include <cstddef>

// Problem constants
#define SEQ   2048
#define BATCH 16
#define HID   512
#define OUT_F 10
#define NLAY  5
#define MROWS (SEQ * BATCH)      // 32768
#define NCOLS (3 * HID)          // 1536
#define BH    (BATCH * HID)      // 8192

// Scan chunking
#define NCH   32
#define CHL   (SEQ / NCH)        // 64 timesteps per chunk
#define SUNROLL 8

// ---------------- device scratch (no allocations allowed) ----------------
__device__ float g_U [(size_t)MROWS * NCOLS];          // 192 MB: [xt | f | r]
__device__ float g_h0[(size_t)MROWS * HID];            // 64 MB ping
__device__ float g_h1[(size_t)MROWS * HID];            // 64 MB pong
__device__ __nv_bfloat16 g_Ahi[(size_t)MROWS * HID];   // 32 MB
__device__ __nv_bfloat16 g_Alo[(size_t)MROWS * HID];   // 32 MB
__device__ __nv_bfloat16 g_Whi[(size_t)NLAY * NCOLS * HID];  // 7.5 MB
__device__ __nv_bfloat16 g_Wlo[(size_t)NLAY * NCOLS * HID];  // 7.5 MB
__device__ float g_P  [(size_t)NCH * BH];              // 1 MB chunk f-products
__device__ float g_S  [(size_t)NCH * BH];              // 1 MB chunk end-states
__device__ float g_Cin[(size_t)NCH * BH];              // 1 MB chunk initial c

// ================= arch-neutral PTX helpers (sm_80+ features only) =======
__device__ __forceinline__ uint32_t smem_to_u32(const void* p) {
    uint32_t a;
    asm("{ .reg .u64 t; cvta.to.shared.u64 t, %1; cvt.u32.u64 %0, t; }"
        : "=r"(a) : "l"(p));
    return a;
}
__device__ __forceinline__ void cp16(uint32_t saddr, const void* g) {
    asm volatile("cp.async.cg.shared.global [%0], [%1], 16;"
                 :: "r"(saddr), "l"(g) : "memory");
}
__device__ __forceinline__ void cp_commit() {
    asm volatile("cp.async.commit_group;" ::: "memory");
}
template <int N>
__device__ __forceinline__ void cp_wait() {
    asm volatile("cp.async.wait_group %0;" :: "n"(N) : "memory");
}
__device__ __forceinline__ void ldsm_x4(uint32_t (&r)[4], uint32_t addr) {
    asm volatile("ldmatrix.sync.aligned.m8n8.x4.shared.b16 {%0,%1,%2,%3}, [%4];"
                 : "=r"(r[0]), "=r"(r[1]), "=r"(r[2]), "=r"(r[3])
                 : "r"(addr));
}
__device__ __forceinline__ void mma_bf16(float (&d)[4], const uint32_t (&a)[4],
                                         uint32_t b0, uint32_t b1) {
    asm volatile(
        "mma.sync.aligned.m16n8k16.row.col.f32.bf16.bf16.f32 "
        "{%0,%1,%2,%3}, {%4,%5,%6,%7}, {%8,%9}, {%0,%1,%2,%3};"
        : "+f"(d[0]), "+f"(d[1]), "+f"(d[2]), "+f"(d[3])
        : "r"(a[0]), "r"(a[1]), "r"(a[2]), "r"(a[3]), "r"(b0), "r"(b1));
}

// ============================================================
// Split fp32 -> (hi, lo) bf16.  n4 = element_count / 4.
// ============================================================
__global__ void split_bf16(const float* __restrict__ in,
                           __nv_bfloat16* __restrict__ hi,
                           __nv_bfloat16* __restrict__ lo, int n4) {
    int i = blockIdx.x * blockDim.x + threadIdx.x;
    if (i >= n4) return;
    float4 v = reinterpret_cast<const float4*>(in)[i];
    const float* pv = &v.x;
    __nv_bfloat16 h[4], l[4];
#pragma unroll
    for (int j = 0; j < 4; j++) {
        h[j] = __float2bfloat16(pv[j]);
        l[j] = __float2bfloat16(pv[j] - __bfloat162float(h[j]));
    }
    reinterpret_cast<uint2*>(hi)[i] = *reinterpret_cast<uint2*>(h);
    reinterpret_cast<uint2*>(lo)[i] = *reinterpret_cast<uint2*>(l);
}

// ============================================================
// Tensor-core GEMM via mma.sync (bf16 2-term split, fp32 accum):
//   U[M=32768, N=1536] = A[M,512] * W[N,512]^T
// CTA tile 128x128, BK=64, 3-stage cp.async pipeline.
// 8 warps: warp tile 32(M) x 64(N) -> 2 x 8 fragments.
// B fragments via ldmatrix.x4 (2 n-tiles + both k-halves per op).
// Epilogue: cols >= 512 -> sigmoid(u + bias[n-512]).
// ============================================================
#define BK 64
#define PITCH_B 144
#define TILE_B (128 * PITCH_B)           // 18432 B per (128 x 64 bf16) tile
#define STAGE_B (4 * TILE_B)             // Ahi|Alo|Bhi|Blo = 73728 B
#define NSTAGE 3
#define SMEM_GEMM (NSTAGE * STAGE_B)     // 221184 B

__device__ __forceinline__ void issue_stage(
    uint32_t sbase, const __nv_bfloat16* __restrict__ Ahi,
    const __nv_bfloat16* __restrict__ Alo,
    const __nv_bfloat16* __restrict__ Whi,
    const __nv_bfloat16* __restrict__ Wlo,
    int bm, int bn, int k0, int tid)
{
#pragma unroll
    for (int i = 0; i < 16; i++) {
        int c   = tid + i * 256;          // 0..4095
        int idx = c & 1023;
        int row = idx >> 3;               // 0..127
        int kc  = idx & 7;                // 16B chunk within 128B row
        uint32_t sa = sbase + (uint32_t)((i >> 2) * TILE_B)
                    + (uint32_t)(row * PITCH_B + kc * 16);
        const __nv_bfloat16* src;
        const int t = i >> 2;
        if      (t == 0) src = Ahi + (size_t)(bm + row) * HID + k0 + kc * 8;
        else if (t == 1) src = Alo + (size_t)(bm + row) * HID + k0 + kc * 8;
        else if (t == 2) src = Whi + (size_t)(bn + row) * HID + k0 + kc * 8;
        else             src = Wlo + (size_t)(bn + row) * HID + k0 + kc * 8;
        cp16(sa, src);
    }
    cp_commit();
}

__global__ void __launch_bounds__(256, 1)
sru_gemm_mma(const __nv_bfloat16* __restrict__ Ahi,
             const __nv_bfloat16* __restrict__ Alo,
             const __nv_bfloat16* __restrict__ Whi,
             const __nv_bfloat16* __restrict__ Wlo,
             const float* __restrict__ bias,
             float* __restrict__ U)
{
    extern __shared__ char smem[];
    const uint32_t sb = smem_to_u32(smem);

    const int tid    = threadIdx.x;
    const int wid    = tid >> 5;
    const int lane   = tid & 31;
    const int group  = lane >> 2;         // 0..7
    const int tid4   = lane & 3;          // 0..3
    const int m_off  = (wid & 3) * 32;
    const int n_off  = (wid >> 2) * 64;
    const int bn     = blockIdx.x * 128;
    const int bm     = blockIdx.y * 128;
    const bool gate  = (bn >= HID);

    // ldmatrix per-lane offsets
    // A (x4): tiles = rows 0-7/k0, rows 8-15/k0, rows 0-7/k8, rows 8-15/k8
    const int a_row = (lane & 7) + ((lane >> 3) & 1) * 8;   // 0..15
    const int a_kb  = ((lane >> 4) & 1) * 8;                // 0 or 8
    // B (x4): tiles = n0-7/k0, n0-7/k8, n8-15/k0, n8-15/k8
    const int b_row = (lane & 7) + ((lane >> 4) & 1) * 8;   // n within 16
    const int b_kb  = ((lane >> 3) & 1) * 8;                // 0 or 8

    float acc[2][8][4];
#pragma unroll
    for (int mi = 0; mi < 2; mi++)
#pragma unroll
        for (int ni = 0; ni < 8; ni++)
#pragma unroll
            for (int q = 0; q < 4; q++) acc[mi][ni][q] = 0.f;

    issue_stage(sb + 0 * STAGE_B, Ahi, Alo, Whi, Wlo, bm, bn, 0,  tid);
    issue_stage(sb + 1 * STAGE_B, Ahi, Alo, Whi, Wlo, bm, bn, BK, tid);

#pragma unroll 1
    for (int s = 0; s < HID / BK; s++) {               // 8 stages
        if (s < 7) cp_wait<1>(); else cp_wait<0>();
        __syncthreads();

        if (s + 2 < HID / BK)
            issue_stage(sb + ((s + 2) % NSTAGE) * STAGE_B,
                        Ahi, Alo, Whi, Wlo, bm, bn, (s + 2) * BK, tid);

        const uint32_t st  = sb + (s % NSTAGE) * STAGE_B;
        const uint32_t sAh = st;
        const uint32_t sAl = st + TILE_B;
        const uint32_t sBh = st + 2 * TILE_B;
        const uint32_t sBl = st + 3 * TILE_B;

#pragma unroll
        for (int kk = 0; kk < BK / 16; kk++) {
            const int kbase = kk * 16;
            uint32_t a_hi[2][4], a_lo[2][4];
#pragma unroll
            for (int mi = 0; mi < 2; mi++) {
                uint32_t ao = (uint32_t)((m_off + mi * 16 + a_row) * PITCH_B
                                         + (kbase + a_kb) * 2);
                ldsm_x4(a_hi[mi], sAh + ao);
                ldsm_x4(a_lo[mi], sAl + ao);
            }
            // B: 4 nj pairs x {hi,lo}; x4 gives (ni, k0),(ni, k8),(ni+1, k0),(ni+1, k8)
            uint32_t b_hi[4][4], b_lo[4][4];
#pragma unroll
            for (int nj = 0; nj < 4; nj++) {
                uint32_t bo = (uint32_t)((n_off + nj * 16 + b_row) * PITCH_B
                                         + (kbase + b_kb) * 2);
                ldsm_x4(b_hi[nj], sBh + bo);
                ldsm_x4(b_lo[nj], sBl + bo);
            }
#pragma unroll
            for (int mi = 0; mi < 2; mi++)
#pragma unroll
                for (int ni = 0; ni < 8; ni++) {
                    const int nj = ni >> 1;
                    const int q  = (ni & 1) * 2;     // 0 or 2
                    mma_bf16(acc[mi][ni], a_hi[mi], b_hi[nj][q], b_hi[nj][q + 1]);
                    mma_bf16(acc[mi][ni], a_hi[mi], b_lo[nj][q], b_lo[nj][q + 1]);
                    mma_bf16(acc[mi][ni], a_lo[mi], b_hi[nj][q], b_hi[nj][q + 1]);
                }
        }
        __syncthreads();
    }

    // ---- epilogue: bias + sigmoid on gate cols, float2 stores ----
#pragma unroll
    for (int mi = 0; mi < 2; mi++) {
        const int row0 = bm + m_off + mi * 16 + group;
#pragma unroll
        for (int ni = 0; ni < 8; ni++) {
            const int col = bn + n_off + ni * 8 + tid4 * 2;
            float u0 = acc[mi][ni][0], u1 = acc[mi][ni][1];
            float u2 = acc[mi][ni][2], u3 = acc[mi][ni][3];
            if (gate) {
                const float bz0 = __ldg(&bias[col - HID]);
                const float bz1 = __ldg(&bias[col + 1 - HID]);
                u0 = 1.0f / (1.0f + expf(-(u0 + bz0)));
                u1 = 1.0f / (1.0f + expf(-(u1 + bz1)));
                u2 = 1.0f / (1.0f + expf(-(u2 + bz0)));
                u3 = 1.0f / (1.0f + expf(-(u3 + bz1)));
            }
            *reinterpret_cast<float2*>(&U[(size_t)row0 * NCOLS + col]) =
                make_float2(u0, u1);
            *reinterpret_cast<float2*>(&U[(size_t)(row0 + 8) * NCOLS + col]) =
                make_float2(u2, u3);
        }
    }
}

// ============================================================
// Chunked parallel scan.
// pass1: per (chunk, lane): local scan with c0=0 -> P = prod f, S = end c
// pass2: per lane: serial combine of 32 chunk summaries -> Cin per chunk
// pass3: per (chunk, lane): re-stream with c = Cin; highway; write
//        h (fp32) and the bf16 hi/lo split for the next layer's GEMM.
// ============================================================
__global__ void __launch_bounds__(256)
scan_pass1(const float* __restrict__ U, float* __restrict__ P, float* __restrict__ S) {
    int gid  = blockIdx.x * blockDim.x + threadIdx.x;   // 0 .. NCH*BH-1
    int lane = gid & (BH - 1);
    int kc   = gid >> 13;
    int b = lane >> 9, h = lane & (HID - 1);
    int l0 = kc * CHL;

    float c = 0.f, p = 1.f;
    for (int l = l0; l < l0 + CHL; l += SUNROLL) {
        float f[SUNROLL], xt[SUNROLL];
#pragma unroll
        for (int u = 0; u < SUNROLL; u++) {
            const float* up = U + ((size_t)(l + u) * BATCH + b) * NCOLS + h;
            xt[u] = up[0];
            f [u] = up[HID];
        }
#pragma unroll
        for (int u = 0; u < SUNROLL; u++) {
            c = fmaf(f[u], c - xt[u], xt[u]);
            p *= f[u];
        }
    }
    P[(size_t)kc * BH + lane] = p;
    S[(size_t)kc * BH + lane] = c;
}

__global__ void __launch_bounds__(256)
scan_pass2(const float* __restrict__ P, const float* __restrict__ S,
           float* __restrict__ Cin) {
    int lane = blockIdx.x * blockDim.x + threadIdx.x;   // 0..BH-1
    float c = 0.f;
#pragma unroll
    for (int k = 0; k < NCH; k++) {
        Cin[(size_t)k * BH + lane] = c;
        c = fmaf(P[(size_t)k * BH + lane], c, S[(size_t)k * BH + lane]);
    }
}

__global__ void __launch_bounds__(256)
scan_pass3(const float* __restrict__ U, const float* __restrict__ xin,
           const float* __restrict__ Cin, float* __restrict__ hout,
           __nv_bfloat16* __restrict__ hhi, __nv_bfloat16* __restrict__ hlo) {
    int gid  = blockIdx.x * blockDim.x + threadIdx.x;
    int lane = gid & (BH - 1);
    int kc   = gid >> 13;
    int b = lane >> 9, h = lane & (HID - 1);
    int l0 = kc * CHL;

    float c = Cin[(size_t)kc * BH + lane];
    for (int l = l0; l < l0 + CHL; l += SUNROLL) {
        float f[SUNROLL], xt[SUNROLL], r[SUNROLL], xv[SUNROLL];
#pragma unroll
        for (int u = 0; u < SUNROLL; u++) {
            size_t row = (size_t)(l + u) * BATCH + b;
            const float* up = U + row * NCOLS + h;
            xt[u] = up[0];
            f [u] = up[HID];
            r [u] = up[2 * HID];
            xv[u] = xin[row * HID + h];
        }
#pragma unroll
        for (int u = 0; u < SUNROLL; u++) {
            c = fmaf(f[u], c - xt[u], xt[u]);
            float hv = fmaf(r[u], c - xv[u], xv[u]);
            size_t idx = ((size_t)(l + u) * BATCH + b) * HID + h;
            hout[idx] = hv;
            __nv_bfloat16 hi = __float2bfloat16(hv);
            hhi[idx] = hi;
            hlo[idx] = __float2bfloat16(hv - __bfloat162float(hi));
        }
    }
}

// ============================================================
// Final FC (known-good)
// ============================================================
__global__ void __launch_bounds__(256)
fc_kernel(const float* __restrict__ Hf, const float* __restrict__ fcW,
          const float* __restrict__ fcb, float* __restrict__ out) {
    __shared__ float Wsm[OUT_F * HID];
    int tid = threadIdx.x;
    for (int i = tid; i < OUT_F * HID; i += 256) Wsm[i] = fcW[i];
    __syncthreads();

    int warp = tid >> 5, lane = tid & 31;
    int row = blockIdx.x * 8 + warp;
    const float* hp = Hf + (size_t)row * HID;

    float acc[OUT_F];
#pragma unroll
    for (int n = 0; n < OUT_F; n++) acc[n] = 0.f;

    for (int k = lane; k < HID; k += 32) {
        float xv = hp[k];
#pragma unroll
        for (int n = 0; n < OUT_F; n++)
            acc[n] = fmaf(xv, Wsm[n * HID + k], acc[n]);
    }
#pragma unroll
    for (int n = 0; n < OUT_F; n++) {
        float v = acc[n];
        v += __shfl_xor_sync(0xFFFFFFFFu, v, 16);
        v += __shfl_xor_sync(0xFFFFFFFFu, v, 8);
        v += __shfl_xor_sync(0xFFFFFFFFu, v, 4);
        v += __shfl_xor_sync(0xFFFFFFFFu, v, 2);
        v += __shfl_xor_sync(0xFFFFFFFFu, v, 1);
        if (lane == 0) out[(size_t)row * OUT_F + n] = v + fcb[n];
    }
}

// ============================================================
// Host launcher (graph-capturable: kernel launches only)
// ============================================================
extern "C" void kernel_launch(void* const* d_in, const int* in_sizes, int n_in,
                              void* d_out, int out_size) {
    const float* x    = (const float*)d_in[0];
    const float* Ws   = (const float*)d_in[1];
    const float* bs   = (const float*)d_in[2];
    const float* fcW  = (const float*)d_in[3];
    const float* fcb  = (const float*)d_in[4];
    float* out        = (float*)d_out;

    float *U, *h0, *h1, *P, *S, *Cin;
    __nv_bfloat16 *Ahi, *Alo, *Whi, *Wlo;
    cudaGetSymbolAddress((void**)&U,   g_U);
    cudaGetSymbolAddress((void**)&h0,  g_h0);
    cudaGetSymbolAddress((void**)&h1,  g_h1);
    cudaGetSymbolAddress((void**)&Ahi, g_Ahi);
    cudaGetSymbolAddress((void**)&Alo, g_Alo);
    cudaGetSymbolAddress((void**)&Whi, g_Whi);
    cudaGetSymbolAddress((void**)&Wlo, g_Wlo);
    cudaGetSymbolAddress((void**)&P,   g_P);
    cudaGetSymbolAddress((void**)&S,   g_S);
    cudaGetSymbolAddress((void**)&Cin, g_Cin);

    cudaFuncSetAttribute(sru_gemm_mma,
                         cudaFuncAttributeMaxDynamicSharedMemorySize, SMEM_GEMM);

    const int nA4   = MROWS * HID / 4;
    const int nWall = NLAY * NCOLS * HID / 4;
    dim3 gm_grid(NCOLS / 128, MROWS / 128);   // (12, 256)
    const int scan_grid = NCH * BH / 256;     // 1024

    // One-time splits: all layer weights, and the layer-0 activations.
    split_bf16<<<(nWall + 255) / 256, 256>>>(Ws, Whi, Wlo, nWall);
    split_bf16<<<(nA4 + 255) / 256, 256>>>(x, Ahi, Alo, nA4);

    const float* cur = x;
    for (int l = 0; l < NLAY; l++) {
        const size_t woff = (size_t)l * NCOLS * HID;
        sru_gemm_mma<<<gm_grid, 256, SMEM_GEMM>>>(Ahi, Alo, Whi + woff, Wlo + woff,
                                                  bs + (size_t)l * (2 * HID), U);
        float* hout = (l & 1) ? h1 : h0;
        scan_pass1<<<scan_grid, 256>>>(U, P, S);
        scan_pass2<<<BH / 256, 256>>>(P, S, Cin);
        scan_pass3<<<scan_grid, 256>>>(U, cur, Cin, hout, Ahi, Alo);
        cur = hout;
    }
    fc_kernel<<<MROWS / 8, 256>>>(cur, fcW, fcb, out);
}

// round 8
// speedup vs baseline: 2.5895x; 1.1057x over previous
#include <cuda_runtime.h>
#include <cuda_bf16.h>
#include <cstdint>
#include <cstddef>

// Problem constants
#define SEQ   2048
#define BATCH 16
#define HID   512
#define OUT_F 10
#define NLAY  5
#define MROWS (SEQ * BATCH)      // 32768
#define NCOLS (3 * HID)          // 1536
#define BH    (BATCH * HID)      // 8192

// Scan chunking
#define NCH   32
#define CHL   (SEQ / NCH)        // 64 timesteps per chunk
#define SUNROLL 8

// ---------------- device scratch (no allocations allowed) ----------------
__device__ float g_U [(size_t)MROWS * NCOLS];          // 192 MB: [xt | f | r]
__device__ float g_h0[(size_t)MROWS * HID];            // 64 MB ping
__device__ float g_h1[(size_t)MROWS * HID];            // 64 MB pong
__device__ __nv_bfloat16 g_Ahi[(size_t)MROWS * HID];   // 32 MB
__device__ __nv_bfloat16 g_Alo[(size_t)MROWS * HID];   // 32 MB
__device__ __nv_bfloat16 g_Whi[(size_t)NLAY * NCOLS * HID];  // 7.5 MB
__device__ __nv_bfloat16 g_Wlo[(size_t)NLAY * NCOLS * HID];  // 7.5 MB
__device__ float g_P  [(size_t)NCH * BH];              // 1 MB chunk f-products
__device__ float g_S  [(size_t)NCH * BH];              // 1 MB chunk end-states
__device__ float g_Cin[(size_t)NCH * BH];              // 1 MB chunk initial c

// ================= arch-neutral PTX helpers (sm_80+ features only) =======
__device__ __forceinline__ uint32_t smem_to_u32(const void* p) {
    uint32_t a;
    asm("{ .reg .u64 t; cvta.to.shared.u64 t, %1; cvt.u32.u64 %0, t; }"
        : "=r"(a) : "l"(p));
    return a;
}
__device__ __forceinline__ void cp16(uint32_t saddr, const void* g) {
    asm volatile("cp.async.cg.shared.global [%0], [%1], 16;"
                 :: "r"(saddr), "l"(g) : "memory");
}
__device__ __forceinline__ void cp_commit() {
    asm volatile("cp.async.commit_group;" ::: "memory");
}
template <int N>
__device__ __forceinline__ void cp_wait() {
    asm volatile("cp.async.wait_group %0;" :: "n"(N) : "memory");
}
__device__ __forceinline__ void ldsm_x4(uint32_t (&r)[4], uint32_t addr) {
    asm volatile("ldmatrix.sync.aligned.m8n8.x4.shared.b16 {%0,%1,%2,%3}, [%4];"
                 : "=r"(r[0]), "=r"(r[1]), "=r"(r[2]), "=r"(r[3])
                 : "r"(addr));
}
__device__ __forceinline__ void mma_bf16(float (&d)[4], const uint32_t (&a)[4],
                                         uint32_t b0, uint32_t b1) {
    asm volatile(
        "mma.sync.aligned.m16n8k16.row.col.f32.bf16.bf16.f32 "
        "{%0,%1,%2,%3}, {%4,%5,%6,%7}, {%8,%9}, {%0,%1,%2,%3};"
        : "+f"(d[0]), "+f"(d[1]), "+f"(d[2]), "+f"(d[3])
        : "r"(a[0]), "r"(a[1]), "r"(a[2]), "r"(a[3]), "r"(b0), "r"(b1));
}

// ============================================================
// Split fp32 -> (hi, lo) bf16.  n4 = element_count / 4.
// ============================================================
__global__ void split_bf16(const float* __restrict__ in,
                           __nv_bfloat16* __restrict__ hi,
                           __nv_bfloat16* __restrict__ lo, int n4) {
    int i = blockIdx.x * blockDim.x + threadIdx.x;
    if (i >= n4) return;
    float4 v = reinterpret_cast<const float4*>(in)[i];
    const float* pv = &v.x;
    __nv_bfloat16 h[4], l[4];
#pragma unroll
    for (int j = 0; j < 4; j++) {
        h[j] = __float2bfloat16(pv[j]);
        l[j] = __float2bfloat16(pv[j] - __bfloat162float(h[j]));
    }
    reinterpret_cast<uint2*>(hi)[i] = *reinterpret_cast<uint2*>(h);
    reinterpret_cast<uint2*>(lo)[i] = *reinterpret_cast<uint2*>(l);
}

// ============================================================
// Tensor-core GEMM via mma.sync (bf16 2-term split, fp32 accum):
//   U[M=32768, N=1536] = A[M,512] * W[N,512]^T
// CTA tile 128(M) x 256(N), BK=64, 2-stage cp.async pipeline, 512 thr.
// 16 warps: 4(M) x 4(N), warp tile 32 x 64 -> 2 x 8 fragments.
// Term-major MMA ordering (acc reuse distance 16, no RAW chains).
// Epilogue: cols >= 512 -> sigmoid(u + bias[n-512]).
// ============================================================
#define BK 64
#define PITCH_B 144
#define A_TILE_B (128 * PITCH_B)          // 18432 B  (128 x 64 bf16)
#define B_TILE_B (256 * PITCH_B)          // 36864 B  (256 x 64 bf16)
#define STAGE_B (2 * A_TILE_B + 2 * B_TILE_B)   // 110592 B
#define NSTAGE 2
#define SMEM_GEMM (NSTAGE * STAGE_B)      // 221184 B

__device__ __forceinline__ void issue_stage(
    uint32_t sbase, const __nv_bfloat16* __restrict__ Ahi,
    const __nv_bfloat16* __restrict__ Alo,
    const __nv_bfloat16* __restrict__ Whi,
    const __nv_bfloat16* __restrict__ Wlo,
    int bm, int bn, int k0, int tid)
{
    // 6144 16B-chunks per stage / 512 threads = 12 per thread.
    // chunk map: [0,2048) Ahi|Alo (1024 each), [2048,6144) Whi|Wlo (2048 each)
#pragma unroll
    for (int i = 0; i < 12; i++) {
        int c = tid + i * 512;
        const __nv_bfloat16* src;
        uint32_t toff;
        int row, kc;
        if (i < 4) {                       // A tiles: 128 rows
            int idx = c & 1023;
            row = idx >> 3;  kc = idx & 7;
            src  = (i < 2 ? Ahi : Alo) + (size_t)(bm + row) * HID + k0 + kc * 8;
            toff = (i < 2) ? 0u : (uint32_t)A_TILE_B;
        } else {                           // B tiles: 256 rows
            int idx = (c - 2048) & 2047;
            row = idx >> 3;  kc = idx & 7;
            src  = (i < 8 ? Whi : Wlo) + (size_t)(bn + row) * HID + k0 + kc * 8;
            toff = (i < 8) ? (uint32_t)(2 * A_TILE_B)
                           : (uint32_t)(2 * A_TILE_B + B_TILE_B);
        }
        cp16(sbase + toff + (uint32_t)(row * PITCH_B + kc * 16), src);
    }
    cp_commit();
}

__global__ void __launch_bounds__(512, 1)
sru_gemm_mma(const __nv_bfloat16* __restrict__ Ahi,
             const __nv_bfloat16* __restrict__ Alo,
             const __nv_bfloat16* __restrict__ Whi,
             const __nv_bfloat16* __restrict__ Wlo,
             const float* __restrict__ bias,
             float* __restrict__ U)
{
    extern __shared__ char smem[];
    const uint32_t sb = smem_to_u32(smem);

    const int tid    = threadIdx.x;
    const int wid    = tid >> 5;
    const int lane   = tid & 31;
    const int group  = lane >> 2;         // 0..7
    const int tid4   = lane & 3;          // 0..3
    const int m_off  = (wid & 3) * 32;    // 4 warps over M=128
    const int n_off  = (wid >> 2) * 64;   // 4 warps over N=256
    const int bn     = blockIdx.x * 256;
    const int bm     = blockIdx.y * 128;
    const bool gate  = (bn >= HID);       // 512 % 256 == 0: tile never straddles

    // ldmatrix per-lane offsets
    const int a_row = (lane & 7) + ((lane >> 3) & 1) * 8;   // 0..15
    const int a_kb  = ((lane >> 4) & 1) * 8;                // 0 or 8
    const int b_row = (lane & 7) + ((lane >> 4) & 1) * 8;   // n within 16
    const int b_kb  = ((lane >> 3) & 1) * 8;                // 0 or 8

    float acc[2][8][4];
#pragma unroll
    for (int mi = 0; mi < 2; mi++)
#pragma unroll
        for (int ni = 0; ni < 8; ni++)
#pragma unroll
            for (int q = 0; q < 4; q++) acc[mi][ni][q] = 0.f;

    issue_stage(sb, Ahi, Alo, Whi, Wlo, bm, bn, 0, tid);

#pragma unroll 1
    for (int s = 0; s < HID / BK; s++) {               // 8 stages
        if (s + 1 < HID / BK) {
            issue_stage(sb + ((s + 1) & 1) * STAGE_B,
                        Ahi, Alo, Whi, Wlo, bm, bn, (s + 1) * BK, tid);
            cp_wait<1>();
        } else {
            cp_wait<0>();
        }
        __syncthreads();

        const uint32_t st  = sb + (s & 1) * STAGE_B;
        const uint32_t sAh = st;
        const uint32_t sAl = st + A_TILE_B;
        const uint32_t sBh = st + 2 * A_TILE_B;
        const uint32_t sBl = st + 2 * A_TILE_B + B_TILE_B;

#pragma unroll
        for (int kk = 0; kk < BK / 16; kk++) {
            const int kbase = kk * 16;
            uint32_t a_hi[2][4], a_lo[2][4];
#pragma unroll
            for (int mi = 0; mi < 2; mi++) {
                uint32_t ao = (uint32_t)((m_off + mi * 16 + a_row) * PITCH_B
                                         + (kbase + a_kb) * 2);
                ldsm_x4(a_hi[mi], sAh + ao);
                ldsm_x4(a_lo[mi], sAl + ao);
            }
            uint32_t b_hi[4][4], b_lo[4][4];
#pragma unroll
            for (int nj = 0; nj < 4; nj++) {
                uint32_t bo = (uint32_t)((n_off + nj * 16 + b_row) * PITCH_B
                                         + (kbase + b_kb) * 2);
                ldsm_x4(b_hi[nj], sBh + bo);
                ldsm_x4(b_lo[nj], sBl + bo);
            }
            // term-major: 16 independent MMAs between reuses of any acc
#pragma unroll
            for (int mi = 0; mi < 2; mi++)
#pragma unroll
                for (int ni = 0; ni < 8; ni++) {
                    const int nj = ni >> 1, q = (ni & 1) * 2;
                    mma_bf16(acc[mi][ni], a_hi[mi], b_hi[nj][q], b_hi[nj][q + 1]);
                }
#pragma unroll
            for (int mi = 0; mi < 2; mi++)
#pragma unroll
                for (int ni = 0; ni < 8; ni++) {
                    const int nj = ni >> 1, q = (ni & 1) * 2;
                    mma_bf16(acc[mi][ni], a_hi[mi], b_lo[nj][q], b_lo[nj][q + 1]);
                }
#pragma unroll
            for (int mi = 0; mi < 2; mi++)
#pragma unroll
                for (int ni = 0; ni < 8; ni++) {
                    const int nj = ni >> 1, q = (ni & 1) * 2;
                    mma_bf16(acc[mi][ni], a_lo[mi], b_hi[nj][q], b_hi[nj][q + 1]);
                }
        }
        __syncthreads();
    }

    // ---- epilogue: bias + sigmoid on gate cols, float2 stores ----
#pragma unroll
    for (int mi = 0; mi < 2; mi++) {
        const int row0 = bm + m_off + mi * 16 + group;
#pragma unroll
        for (int ni = 0; ni < 8; ni++) {
            const int col = bn + n_off + ni * 8 + tid4 * 2;
            float u0 = acc[mi][ni][0], u1 = acc[mi][ni][1];
            float u2 = acc[mi][ni][2], u3 = acc[mi][ni][3];
            if (gate) {
                const float bz0 = __ldg(&bias[col - HID]);
                const float bz1 = __ldg(&bias[col + 1 - HID]);
                u0 = 1.0f / (1.0f + expf(-(u0 + bz0)));
                u1 = 1.0f / (1.0f + expf(-(u1 + bz1)));
                u2 = 1.0f / (1.0f + expf(-(u2 + bz0)));
                u3 = 1.0f / (1.0f + expf(-(u3 + bz1)));
            }
            *reinterpret_cast<float2*>(&U[(size_t)row0 * NCOLS + col]) =
                make_float2(u0, u1);
            *reinterpret_cast<float2*>(&U[(size_t)(row0 + 8) * NCOLS + col]) =
                make_float2(u2, u3);
        }
    }
}

// ============================================================
// Chunked parallel scan (known-good, 26us/pass @ 65% DRAM)
// ============================================================
__global__ void __launch_bounds__(256)
scan_pass1(const float* __restrict__ U, float* __restrict__ P, float* __restrict__ S) {
    int gid  = blockIdx.x * blockDim.x + threadIdx.x;   // 0 .. NCH*BH-1
    int lane = gid & (BH - 1);
    int kc   = gid >> 13;
    int b = lane >> 9, h = lane & (HID - 1);
    int l0 = kc * CHL;

    float c = 0.f, p = 1.f;
    for (int l = l0; l < l0 + CHL; l += SUNROLL) {
        float f[SUNROLL], xt[SUNROLL];
#pragma unroll
        for (int u = 0; u < SUNROLL; u++) {
            const float* up = U + ((size_t)(l + u) * BATCH + b) * NCOLS + h;
            xt[u] = up[0];
            f [u] = up[HID];
        }
#pragma unroll
        for (int u = 0; u < SUNROLL; u++) {
            c = fmaf(f[u], c - xt[u], xt[u]);
            p *= f[u];
        }
    }
    P[(size_t)kc * BH + lane] = p;
    S[(size_t)kc * BH + lane] = c;
}

__global__ void __launch_bounds__(256)
scan_pass2(const float* __restrict__ P, const float* __restrict__ S,
           float* __restrict__ Cin) {
    int lane = blockIdx.x * blockDim.x + threadIdx.x;   // 0..BH-1
    float c = 0.f;
#pragma unroll
    for (int k = 0; k < NCH; k++) {
        Cin[(size_t)k * BH + lane] = c;
        c = fmaf(P[(size_t)k * BH + lane], c, S[(size_t)k * BH + lane]);
    }
}

__global__ void __launch_bounds__(256)
scan_pass3(const float* __restrict__ U, const float* __restrict__ xin,
           const float* __restrict__ Cin, float* __restrict__ hout,
           __nv_bfloat16* __restrict__ hhi, __nv_bfloat16* __restrict__ hlo) {
    int gid  = blockIdx.x * blockDim.x + threadIdx.x;
    int lane = gid & (BH - 1);
    int kc   = gid >> 13;
    int b = lane >> 9, h = lane & (HID - 1);
    int l0 = kc * CHL;

    float c = Cin[(size_t)kc * BH + lane];
    for (int l = l0; l < l0 + CHL; l += SUNROLL) {
        float f[SUNROLL], xt[SUNROLL], r[SUNROLL], xv[SUNROLL];
#pragma unroll
        for (int u = 0; u < SUNROLL; u++) {
            size_t row = (size_t)(l + u) * BATCH + b;
            const float* up = U + row * NCOLS + h;
            xt[u] = up[0];
            f [u] = up[HID];
            r [u] = up[2 * HID];
            xv[u] = xin[row * HID + h];
        }
#pragma unroll
        for (int u = 0; u < SUNROLL; u++) {
            c = fmaf(f[u], c - xt[u], xt[u]);
            float hv = fmaf(r[u], c - xv[u], xv[u]);
            size_t idx = ((size_t)(l + u) * BATCH + b) * HID + h;
            hout[idx] = hv;
            __nv_bfloat16 hi = __float2bfloat16(hv);
            hhi[idx] = hi;
            hlo[idx] = __float2bfloat16(hv - __bfloat162float(hi));
        }
    }
}

// ============================================================
// Final FC (known-good)
// ============================================================
__global__ void __launch_bounds__(256)
fc_kernel(const float* __restrict__ Hf, const float* __restrict__ fcW,
          const float* __restrict__ fcb, float* __restrict__ out) {
    __shared__ float Wsm[OUT_F * HID];
    int tid = threadIdx.x;
    for (int i = tid; i < OUT_F * HID; i += 256) Wsm[i] = fcW[i];
    __syncthreads();

    int warp = tid >> 5, lane = tid & 31;
    int row = blockIdx.x * 8 + warp;
    const float* hp = Hf + (size_t)row * HID;

    float acc[OUT_F];
#pragma unroll
    for (int n = 0; n < OUT_F; n++) acc[n] = 0.f;

    for (int k = lane; k < HID; k += 32) {
        float xv = hp[k];
#pragma unroll
        for (int n = 0; n < OUT_F; n++)
            acc[n] = fmaf(xv, Wsm[n * HID + k], acc[n]);
    }
#pragma unroll
    for (int n = 0; n < OUT_F; n++) {
        float v = acc[n];
        v += __shfl_xor_sync(0xFFFFFFFFu, v, 16);
        v += __shfl_xor_sync(0xFFFFFFFFu, v, 8);
        v += __shfl_xor_sync(0xFFFFFFFFu, v, 4);
        v += __shfl_xor_sync(0xFFFFFFFFu, v, 2);
        v += __shfl_xor_sync(0xFFFFFFFFu, v, 1);
        if (lane == 0) out[(size_t)row * OUT_F + n] = v + fcb[n];
    }
}

// ============================================================
// Host launcher (graph-capturable: kernel launches only)
// ============================================================
extern "C" void kernel_launch(void* const* d_in, const int* in_sizes, int n_in,
                              void* d_out, int out_size) {
    const float* x    = (const float*)d_in[0];
    const float* Ws   = (const float*)d_in[1];
    const float* bs   = (const float*)d_in[2];
    const float* fcW  = (const float*)d_in[3];
    const float* fcb  = (const float*)d_in[4];
    float* out        = (float*)d_out;

    float *U, *h0, *h1, *P, *S, *Cin;
    __nv_bfloat16 *Ahi, *Alo, *Whi, *Wlo;
    cudaGetSymbolAddress((void**)&U,   g_U);
    cudaGetSymbolAddress((void**)&h0,  g_h0);
    cudaGetSymbolAddress((void**)&h1,  g_h1);
    cudaGetSymbolAddress((void**)&Ahi, g_Ahi);
    cudaGetSymbolAddress((void**)&Alo, g_Alo);
    cudaGetSymbolAddress((void**)&Whi, g_Whi);
    cudaGetSymbolAddress((void**)&Wlo, g_Wlo);
    cudaGetSymbolAddress((void**)&P,   g_P);
    cudaGetSymbolAddress((void**)&S,   g_S);
    cudaGetSymbolAddress((void**)&Cin, g_Cin);

    cudaFuncSetAttribute(sru_gemm_mma,
                         cudaFuncAttributeMaxDynamicSharedMemorySize, SMEM_GEMM);

    const int nA4   = MROWS * HID / 4;
    const int nWall = NLAY * NCOLS * HID / 4;
    dim3 gm_grid(NCOLS / 256, MROWS / 128);   // (6, 256)
    const int scan_grid = NCH * BH / 256;     // 1024

    // One-time splits: all layer weights, and the layer-0 activations.
    split_bf16<<<(nWall + 255) / 256, 256>>>(Ws, Whi, Wlo, nWall);
    split_bf16<<<(nA4 + 255) / 256, 256>>>(x, Ahi, Alo, nA4);

    const float* cur = x;
    for (int l = 0; l < NLAY; l++) {
        const size_t woff = (size_t)l * NCOLS * HID;
        sru_gemm_mma<<<gm_grid, 512, SMEM_GEMM>>>(Ahi, Alo, Whi + woff, Wlo + woff,
                                                  bs + (size_t)l * (2 * HID), U);
        float* hout = (l & 1) ? h1 : h0;
        scan_pass1<<<scan_grid, 256>>>(U, P, S);
        scan_pass2<<<BH / 256, 256>>>(P, S, Cin);
        scan_pass3<<<scan_grid, 256>>>(U, cur, Cin, hout, Ahi, Alo);
        cur = hout;
    }
    fc_kernel<<<MROWS / 8, 256>>>(cur, fcW, fcb, out);
}

// round 9
// speedup vs baseline: 3.4846x; 1.3456x over previous
#include <cuda_runtime.h>
#include <cuda_fp16.h>
#include <cuda_bf16.h>
#include <cstdint>
#include <cstddef>

// Problem constants
#define SEQ   2048
#define BATCH 16
#define HID   512
#define OUT_F 10
#define NLAY  5
#define MROWS (SEQ * BATCH)      // 32768
#define NCOLS (3 * HID)          // 1536
#define BH    (BATCH * HID)      // 8192

// Scan chunking
#define NCH   32
#define CHL   (SEQ / NCH)        // 64 timesteps per chunk
#define SUNROLL 8

// ---------------- device scratch (no allocations allowed) ----------------
__device__ float g_U [(size_t)MROWS * NCOLS];          // 192 MB: [xt | f | r]
__device__ float g_h0[(size_t)MROWS * HID];            // 64 MB ping
__device__ float g_h1[(size_t)MROWS * HID];            // 64 MB pong
__device__ __half g_Ah [(size_t)MROWS * HID];          // 32 MB activations fp16
__device__ __half g_Whi[(size_t)NLAY * NCOLS * HID];   // 7.5 MB weight hi
__device__ __half g_Wlo[(size_t)NLAY * NCOLS * HID];   // 7.5 MB weight lo
__device__ float g_P  [(size_t)NCH * BH];              // 1 MB chunk f-products
__device__ float g_S  [(size_t)NCH * BH];              // 1 MB chunk end-states
__device__ float g_Cin[(size_t)NCH * BH];              // 1 MB chunk initial c

// ================= arch-neutral PTX helpers (sm_80+ features only) =======
__device__ __forceinline__ uint32_t smem_to_u32(const void* p) {
    uint32_t a;
    asm("{ .reg .u64 t; cvta.to.shared.u64 t, %1; cvt.u32.u64 %0, t; }"
        : "=r"(a) : "l"(p));
    return a;
}
__device__ __forceinline__ void cp16(uint32_t saddr, const void* g) {
    asm volatile("cp.async.cg.shared.global [%0], [%1], 16;"
                 :: "r"(saddr), "l"(g) : "memory");
}
__device__ __forceinline__ void cp_commit() {
    asm volatile("cp.async.commit_group;" ::: "memory");
}
template <int N>
__device__ __forceinline__ void cp_wait() {
    asm volatile("cp.async.wait_group %0;" :: "n"(N) : "memory");
}
__device__ __forceinline__ void ldsm_x4(uint32_t (&r)[4], uint32_t addr) {
    asm volatile("ldmatrix.sync.aligned.m8n8.x4.shared.b16 {%0,%1,%2,%3}, [%4];"
                 : "=r"(r[0]), "=r"(r[1]), "=r"(r[2]), "=r"(r[3])
                 : "r"(addr));
}
__device__ __forceinline__ void mma_fp16(float (&d)[4], const uint32_t (&a)[4],
                                         uint32_t b0, uint32_t b1) {
    asm volatile(
        "mma.sync.aligned.m16n8k16.row.col.f32.f16.f16.f32 "
        "{%0,%1,%2,%3}, {%4,%5,%6,%7}, {%8,%9}, {%0,%1,%2,%3};"
        : "+f"(d[0]), "+f"(d[1]), "+f"(d[2]), "+f"(d[3])
        : "r"(a[0]), "r"(a[1]), "r"(a[2]), "r"(a[3]), "r"(b0), "r"(b1));
}

// ============================================================
// Weight split fp32 -> (hi, lo) fp16.  n4 = element_count / 4.
// ============================================================
__global__ void split_fp16(const float* __restrict__ in,
                           __half* __restrict__ hi,
                           __half* __restrict__ lo, int n4) {
    int i = blockIdx.x * blockDim.x + threadIdx.x;
    if (i >= n4) return;
    float4 v = reinterpret_cast<const float4*>(in)[i];
    const float* pv = &v.x;
    __half h[4], l[4];
#pragma unroll
    for (int j = 0; j < 4; j++) {
        h[j] = __float2half_rn(pv[j]);
        l[j] = __float2half_rn(pv[j] - __half2float(h[j]));
    }
    reinterpret_cast<uint2*>(hi)[i] = *reinterpret_cast<uint2*>(h);
    reinterpret_cast<uint2*>(lo)[i] = *reinterpret_cast<uint2*>(l);
}

// fp32 -> fp16 convert (activations, layer 0)
__global__ void convert_fp16(const float* __restrict__ in,
                             __half* __restrict__ out, int n4) {
    int i = blockIdx.x * blockDim.x + threadIdx.x;
    if (i >= n4) return;
    float4 v = reinterpret_cast<const float4*>(in)[i];
    __half h[4];
    h[0] = __float2half_rn(v.x);  h[1] = __float2half_rn(v.y);
    h[2] = __float2half_rn(v.z);  h[3] = __float2half_rn(v.w);
    reinterpret_cast<uint2*>(out)[i] = *reinterpret_cast<uint2*>(h);
}

// ============================================================
// Tensor-core GEMM via mma.sync (fp16 split, 2 terms, fp32 accum):
//   U[M=32768, N=1536] = A[M,512] * (Whi + Wlo)[N,512]^T
// CTA tile 128(M) x 256(N), BK=64, 2-stage cp.async pipeline, 512 thr.
// 16 warps: 4(M) x 4(N), warp tile 32 x 64 -> 2 x 8 fragments.
// Epilogue: cols >= 512 -> sigmoid(u + bias[n-512]).
// ============================================================
#define BK 64
#define PITCH_B 144
#define A_TILE_B (128 * PITCH_B)          // 18432 B  (128 x 64 fp16)
#define B_TILE_B (256 * PITCH_B)          // 36864 B  (256 x 64 fp16)
#define STAGE_B (A_TILE_B + 2 * B_TILE_B) // 92160 B
#define NSTAGE 2
#define SMEM_GEMM (NSTAGE * STAGE_B)      // 184320 B

__device__ __forceinline__ void issue_stage(
    uint32_t sbase, const __half* __restrict__ Ah,
    const __half* __restrict__ Whi, const __half* __restrict__ Wlo,
    int bm, int bn, int k0, int tid)
{
    // 5120 16B-chunks per stage / 512 threads = 10 per thread.
    // [0,1024) A, [1024,3072) Whi, [3072,5120) Wlo
#pragma unroll
    for (int i = 0; i < 10; i++) {
        int c = tid + i * 512;
        const __half* src;
        uint32_t toff;
        int row, kc;
        if (i < 2) {                       // A: 128 rows
            int idx = c;                   // 0..1023
            row = idx >> 3;  kc = idx & 7;
            src  = Ah + (size_t)(bm + row) * HID + k0 + kc * 8;
            toff = 0u;
        } else if (i < 6) {                // Whi: 256 rows
            int idx = c - 1024;            // 0..2047
            row = idx >> 3;  kc = idx & 7;
            src  = Whi + (size_t)(bn + row) * HID + k0 + kc * 8;
            toff = (uint32_t)A_TILE_B;
        } else {                           // Wlo: 256 rows
            int idx = c - 3072;            // 0..2047
            row = idx >> 3;  kc = idx & 7;
            src  = Wlo + (size_t)(bn + row) * HID + k0 + kc * 8;
            toff = (uint32_t)(A_TILE_B + B_TILE_B);
        }
        cp16(sbase + toff + (uint32_t)(row * PITCH_B + kc * 16), src);
    }
    cp_commit();
}

__global__ void __launch_bounds__(512, 1)
sru_gemm_mma(const __half* __restrict__ Ah,
             const __half* __restrict__ Whi,
             const __half* __restrict__ Wlo,
             const float* __restrict__ bias,
             float* __restrict__ U)
{
    extern __shared__ char smem[];
    const uint32_t sb = smem_to_u32(smem);

    const int tid    = threadIdx.x;
    const int wid    = tid >> 5;
    const int lane   = tid & 31;
    const int group  = lane >> 2;         // 0..7
    const int tid4   = lane & 3;          // 0..3
    const int m_off  = (wid & 3) * 32;    // 4 warps over M=128
    const int n_off  = (wid >> 2) * 64;   // 4 warps over N=256
    const int bn     = blockIdx.x * 256;
    const int bm     = blockIdx.y * 128;
    const bool gate  = (bn >= HID);       // tile never straddles xt/gate split

    // ldmatrix per-lane offsets
    const int a_row = (lane & 7) + ((lane >> 3) & 1) * 8;   // 0..15
    const int a_kb  = ((lane >> 4) & 1) * 8;                // 0 or 8
    const int b_row = (lane & 7) + ((lane >> 4) & 1) * 8;   // n within 16
    const int b_kb  = ((lane >> 3) & 1) * 8;                // 0 or 8

    float acc[2][8][4];
#pragma unroll
    for (int mi = 0; mi < 2; mi++)
#pragma unroll
        for (int ni = 0; ni < 8; ni++)
#pragma unroll
            for (int q = 0; q < 4; q++) acc[mi][ni][q] = 0.f;

    issue_stage(sb, Ah, Whi, Wlo, bm, bn, 0, tid);

#pragma unroll 1
    for (int s = 0; s < HID / BK; s++) {               // 8 stages
        if (s + 1 < HID / BK) {
            issue_stage(sb + ((s + 1) & 1) * STAGE_B,
                        Ah, Whi, Wlo, bm, bn, (s + 1) * BK, tid);
            cp_wait<1>();
        } else {
            cp_wait<0>();
        }
        __syncthreads();

        const uint32_t st  = sb + (s & 1) * STAGE_B;
        const uint32_t sA  = st;
        const uint32_t sBh = st + A_TILE_B;
        const uint32_t sBl = st + A_TILE_B + B_TILE_B;

#pragma unroll
        for (int kk = 0; kk < BK / 16; kk++) {
            const int kbase = kk * 16;
            uint32_t a_f[2][4];
#pragma unroll
            for (int mi = 0; mi < 2; mi++) {
                uint32_t ao = (uint32_t)((m_off + mi * 16 + a_row) * PITCH_B
                                         + (kbase + a_kb) * 2);
                ldsm_x4(a_f[mi], sA + ao);
            }
            uint32_t b_hi[4][4], b_lo[4][4];
#pragma unroll
            for (int nj = 0; nj < 4; nj++) {
                uint32_t bo = (uint32_t)((n_off + nj * 16 + b_row) * PITCH_B
                                         + (kbase + b_kb) * 2);
                ldsm_x4(b_hi[nj], sBh + bo);
                ldsm_x4(b_lo[nj], sBl + bo);
            }
            // term-major: 16 independent MMAs between reuses of any acc
#pragma unroll
            for (int mi = 0; mi < 2; mi++)
#pragma unroll
                for (int ni = 0; ni < 8; ni++) {
                    const int nj = ni >> 1, q = (ni & 1) * 2;
                    mma_fp16(acc[mi][ni], a_f[mi], b_hi[nj][q], b_hi[nj][q + 1]);
                }
#pragma unroll
            for (int mi = 0; mi < 2; mi++)
#pragma unroll
                for (int ni = 0; ni < 8; ni++) {
                    const int nj = ni >> 1, q = (ni & 1) * 2;
                    mma_fp16(acc[mi][ni], a_f[mi], b_lo[nj][q], b_lo[nj][q + 1]);
                }
        }
        __syncthreads();
    }

    // ---- epilogue: bias + fast sigmoid on gate cols, float2 stores ----
#pragma unroll
    for (int mi = 0; mi < 2; mi++) {
        const int row0 = bm + m_off + mi * 16 + group;
#pragma unroll
        for (int ni = 0; ni < 8; ni++) {
            const int col = bn + n_off + ni * 8 + tid4 * 2;
            float u0 = acc[mi][ni][0], u1 = acc[mi][ni][1];
            float u2 = acc[mi][ni][2], u3 = acc[mi][ni][3];
            if (gate) {
                const float bz0 = __ldg(&bias[col - HID]);
                const float bz1 = __ldg(&bias[col + 1 - HID]);
                u0 = __fdividef(1.0f, 1.0f + __expf(-(u0 + bz0)));
                u1 = __fdividef(1.0f, 1.0f + __expf(-(u1 + bz1)));
                u2 = __fdividef(1.0f, 1.0f + __expf(-(u2 + bz0)));
                u3 = __fdividef(1.0f, 1.0f + __expf(-(u3 + bz1)));
            }
            *reinterpret_cast<float2*>(&U[(size_t)row0 * NCOLS + col]) =
                make_float2(u0, u1);
            *reinterpret_cast<float2*>(&U[(size_t)(row0 + 8) * NCOLS + col]) =
                make_float2(u2, u3);
        }
    }
}

// ============================================================
// Chunked parallel scan (known-good structure)
// ============================================================
__global__ void __launch_bounds__(256)
scan_pass1(const float* __restrict__ U, float* __restrict__ P, float* __restrict__ S) {
    int gid  = blockIdx.x * blockDim.x + threadIdx.x;   // 0 .. NCH*BH-1
    int lane = gid & (BH - 1);
    int kc   = gid >> 13;
    int b = lane >> 9, h = lane & (HID - 1);
    int l0 = kc * CHL;

    float c = 0.f, p = 1.f;
    for (int l = l0; l < l0 + CHL; l += SUNROLL) {
        float f[SUNROLL], xt[SUNROLL];
#pragma unroll
        for (int u = 0; u < SUNROLL; u++) {
            const float* up = U + ((size_t)(l + u) * BATCH + b) * NCOLS + h;
            xt[u] = up[0];
            f [u] = up[HID];
        }
#pragma unroll
        for (int u = 0; u < SUNROLL; u++) {
            c = fmaf(f[u], c - xt[u], xt[u]);
            p *= f[u];
        }
    }
    P[(size_t)kc * BH + lane] = p;
    S[(size_t)kc * BH + lane] = c;
}

__global__ void __launch_bounds__(256)
scan_pass2(const float* __restrict__ P, const float* __restrict__ S,
           float* __restrict__ Cin) {
    int lane = blockIdx.x * blockDim.x + threadIdx.x;   // 0..BH-1
    float c = 0.f;
#pragma unroll
    for (int k = 0; k < NCH; k++) {
        Cin[(size_t)k * BH + lane] = c;
        c = fmaf(P[(size_t)k * BH + lane], c, S[(size_t)k * BH + lane]);
    }
}

__global__ void __launch_bounds__(256)
scan_pass3(const float* __restrict__ U, const float* __restrict__ xin,
           const float* __restrict__ Cin, float* __restrict__ hout,
           __half* __restrict__ hfp16) {
    int gid  = blockIdx.x * blockDim.x + threadIdx.x;
    int lane = gid & (BH - 1);
    int kc   = gid >> 13;
    int b = lane >> 9, h = lane & (HID - 1);
    int l0 = kc * CHL;

    float c = Cin[(size_t)kc * BH + lane];
    for (int l = l0; l < l0 + CHL; l += SUNROLL) {
        float f[SUNROLL], xt[SUNROLL], r[SUNROLL], xv[SUNROLL];
#pragma unroll
        for (int u = 0; u < SUNROLL; u++) {
            size_t row = (size_t)(l + u) * BATCH + b;
            const float* up = U + row * NCOLS + h;
            xt[u] = up[0];
            f [u] = up[HID];
            r [u] = up[2 * HID];
            xv[u] = xin[row * HID + h];
        }
#pragma unroll
        for (int u = 0; u < SUNROLL; u++) {
            c = fmaf(f[u], c - xt[u], xt[u]);
            float hv = fmaf(r[u], c - xv[u], xv[u]);
            size_t idx = ((size_t)(l + u) * BATCH + b) * HID + h;
            hout[idx] = hv;
            hfp16[idx] = __float2half_rn(hv);
        }
    }
}

// ============================================================
// Final FC (known-good)
// ============================================================
__global__ void __launch_bounds__(256)
fc_kernel(const float* __restrict__ Hf, const float* __restrict__ fcW,
          const float* __restrict__ fcb, float* __restrict__ out) {
    __shared__ float Wsm[OUT_F * HID];
    int tid = threadIdx.x;
    for (int i = tid; i < OUT_F * HID; i += 256) Wsm[i] = fcW[i];
    __syncthreads();

    int warp = tid >> 5, lane = tid & 31;
    int row = blockIdx.x * 8 + warp;
    const float* hp = Hf + (size_t)row * HID;

    float acc[OUT_F];
#pragma unroll
    for (int n = 0; n < OUT_F; n++) acc[n] = 0.f;

    for (int k = lane; k < HID; k += 32) {
        float xv = hp[k];
#pragma unroll
        for (int n = 0; n < OUT_F; n++)
            acc[n] = fmaf(xv, Wsm[n * HID + k], acc[n]);
    }
#pragma unroll
    for (int n = 0; n < OUT_F; n++) {
        float v = acc[n];
        v += __shfl_xor_sync(0xFFFFFFFFu, v, 16);
        v += __shfl_xor_sync(0xFFFFFFFFu, v, 8);
        v += __shfl_xor_sync(0xFFFFFFFFu, v, 4);
        v += __shfl_xor_sync(0xFFFFFFFFu, v, 2);
        v += __shfl_xor_sync(0xFFFFFFFFu, v, 1);
        if (lane == 0) out[(size_t)row * OUT_F + n] = v + fcb[n];
    }
}

// ============================================================
// Host launcher (graph-capturable: kernel launches only)
// ============================================================
extern "C" void kernel_launch(void* const* d_in, const int* in_sizes, int n_in,
                              void* d_out, int out_size) {
    const float* x    = (const float*)d_in[0];
    const float* Ws   = (const float*)d_in[1];
    const float* bs   = (const float*)d_in[2];
    const float* fcW  = (const float*)d_in[3];
    const float* fcb  = (const float*)d_in[4];
    float* out        = (float*)d_out;

    float *U, *h0, *h1, *P, *S, *Cin;
    __half *Ah, *Whi, *Wlo;
    cudaGetSymbolAddress((void**)&U,   g_U);
    cudaGetSymbolAddress((void**)&h0,  g_h0);
    cudaGetSymbolAddress((void**)&h1,  g_h1);
    cudaGetSymbolAddress((void**)&Ah,  g_Ah);
    cudaGetSymbolAddress((void**)&Whi, g_Whi);
    cudaGetSymbolAddress((void**)&Wlo, g_Wlo);
    cudaGetSymbolAddress((void**)&P,   g_P);
    cudaGetSymbolAddress((void**)&S,   g_S);
    cudaGetSymbolAddress((void**)&Cin, g_Cin);

    cudaFuncSetAttribute(sru_gemm_mma,
                         cudaFuncAttributeMaxDynamicSharedMemorySize, SMEM_GEMM);

    const int nA4   = MROWS * HID / 4;
    const int nWall = NLAY * NCOLS * HID / 4;
    dim3 gm_grid(NCOLS / 256, MROWS / 128);   // (6, 256)
    const int scan_grid = NCH * BH / 256;     // 1024

    // One-time: split all layer weights, convert layer-0 activations.
    split_fp16<<<(nWall + 255) / 256, 256>>>(Ws, Whi, Wlo, nWall);
    convert_fp16<<<(nA4 + 255) / 256, 256>>>(x, Ah, nA4);

    const float* cur = x;
    for (int l = 0; l < NLAY; l++) {
        const size_t woff = (size_t)l * NCOLS * HID;
        sru_gemm_mma<<<gm_grid, 512, SMEM_GEMM>>>(Ah, Whi + woff, Wlo + woff,
                                                  bs + (size_t)l * (2 * HID), U);
        float* hout = (l & 1) ? h1 : h0;
        scan_pass1<<<scan_grid, 256>>>(U, P, S);
        scan_pass2<<<BH / 256, 256>>>(P, S, Cin);
        scan_pass3<<<scan_grid, 256>>>(U, cur, Cin, hout, Ah);
        cur = hout;
    }
    fc_kernel<<<MROWS / 8, 256>>>(cur, fcW, fcb, out);
}

// round 10
// speedup vs baseline: 4.9263x; 1.4137x over previous
#include <cuda_runtime.h>
#include <cuda_fp16.h>
#include <cstdint>
#include <cstddef>

// Problem constants
#define SEQ   2048
#define BATCH 16
#define HID   512
#define OUT_F 10
#define NLAY  5
#define MROWS (SEQ * BATCH)      // 32768
#define NCOLS (3 * HID)          // 1536
#define BH    (BATCH * HID)      // 8192

// Scan chunking
#define NCH   32
#define CHL   (SEQ / NCH)        // 64 timesteps per chunk
#define SUNROLL 8

// ---------------- device scratch (no allocations allowed) ----------------
__device__ float g_U [(size_t)MROWS * NCOLS];          // 192 MB: [xt | f | r]
__device__ float g_h0[(size_t)MROWS * HID];            // 64 MB ping
__device__ float g_h1[(size_t)MROWS * HID];            // 64 MB pong
__device__ __half g_Ah[(size_t)MROWS * HID];           // 32 MB activations fp16
__device__ __half g_Wh[(size_t)NLAY * NCOLS * HID];    // 7.5 MB weights fp16
__device__ float g_P  [(size_t)NCH * BH];              // 1 MB chunk f-products
__device__ float g_S  [(size_t)NCH * BH];              // 1 MB chunk end-states
__device__ float g_Cin[(size_t)NCH * BH];              // 1 MB chunk initial c

// ================= arch-neutral PTX helpers (sm_80+ features only) =======
__device__ __forceinline__ uint32_t smem_to_u32(const void* p) {
    uint32_t a;
    asm("{ .reg .u64 t; cvta.to.shared.u64 t, %1; cvt.u32.u64 %0, t; }"
        : "=r"(a) : "l"(p));
    return a;
}
__device__ __forceinline__ void cp16(uint32_t saddr, const void* g) {
    asm volatile("cp.async.cg.shared.global [%0], [%1], 16;"
                 :: "r"(saddr), "l"(g) : "memory");
}
__device__ __forceinline__ void cp_commit() {
    asm volatile("cp.async.commit_group;" ::: "memory");
}
template <int N>
__device__ __forceinline__ void cp_wait() {
    asm volatile("cp.async.wait_group %0;" :: "n"(N) : "memory");
}
__device__ __forceinline__ void ldsm_x4(uint32_t (&r)[4], uint32_t addr) {
    asm volatile("ldmatrix.sync.aligned.m8n8.x4.shared.b16 {%0,%1,%2,%3}, [%4];"
                 : "=r"(r[0]), "=r"(r[1]), "=r"(r[2]), "=r"(r[3])
                 : "r"(addr));
}
__device__ __forceinline__ void mma_fp16(float (&d)[4], const uint32_t (&a)[4],
                                         uint32_t b0, uint32_t b1) {
    asm volatile(
        "mma.sync.aligned.m16n8k16.row.col.f32.f16.f16.f32 "
        "{%0,%1,%2,%3}, {%4,%5,%6,%7}, {%8,%9}, {%0,%1,%2,%3};"
        : "+f"(d[0]), "+f"(d[1]), "+f"(d[2]), "+f"(d[3])
        : "r"(a[0]), "r"(a[1]), "r"(a[2]), "r"(a[3]), "r"(b0), "r"(b1));
}

// ============================================================
// fp32 -> fp16 convert.  n4 = element_count / 4.
// ============================================================
__global__ void convert_fp16(const float* __restrict__ in,
                             __half* __restrict__ out, int n4) {
    int i = blockIdx.x * blockDim.x + threadIdx.x;
    if (i >= n4) return;
    float4 v = reinterpret_cast<const float4*>(in)[i];
    __half h[4];
    h[0] = __float2half_rn(v.x);  h[1] = __float2half_rn(v.y);
    h[2] = __float2half_rn(v.z);  h[3] = __float2half_rn(v.w);
    reinterpret_cast<uint2*>(out)[i] = *reinterpret_cast<uint2*>(h);
}

// ============================================================
// Tensor-core GEMM via mma.sync (pure fp16, fp32 accum):
//   U[M=32768, N=1536] = A[M,512] * W[N,512]^T
// CTA tile 128(M) x 256(N), BK=64, 3-stage cp.async pipeline, 512 thr.
// 16 warps: 4(M) x 4(N), warp tile 32 x 64 -> 2 x 8 fragments.
// Epilogue: cols >= 512 -> sigmoid(u + bias[n-512]).
// ============================================================
#define BK 64
#define PITCH_B 144
#define A_TILE_B (128 * PITCH_B)          // 18432 B  (128 x 64 fp16)
#define B_TILE_B (256 * PITCH_B)          // 36864 B  (256 x 64 fp16)
#define STAGE_B (A_TILE_B + B_TILE_B)     // 55296 B
#define NSTAGE 3
#define SMEM_GEMM (NSTAGE * STAGE_B)      // 165888 B

__device__ __forceinline__ void issue_stage(
    uint32_t sbase, const __half* __restrict__ Ah,
    const __half* __restrict__ Wh,
    int bm, int bn, int k0, int tid)
{
    // 3072 16B-chunks per stage / 512 threads = 6 per thread.
    // [0,1024) A (128 rows), [1024,3072) W (256 rows)
#pragma unroll
    for (int i = 0; i < 6; i++) {
        int c = tid + i * 512;
        const __half* src;
        uint32_t toff;
        int row, kc;
        if (i < 2) {                       // A: 128 rows
            int idx = c;                   // 0..1023
            row = idx >> 3;  kc = idx & 7;
            src  = Ah + (size_t)(bm + row) * HID + k0 + kc * 8;
            toff = 0u;
        } else {                           // W: 256 rows
            int idx = c - 1024;            // 0..2047
            row = idx >> 3;  kc = idx & 7;
            src  = Wh + (size_t)(bn + row) * HID + k0 + kc * 8;
            toff = (uint32_t)A_TILE_B;
        }
        cp16(sbase + toff + (uint32_t)(row * PITCH_B + kc * 16), src);
    }
    cp_commit();
}

__global__ void __launch_bounds__(512, 1)
sru_gemm_mma(const __half* __restrict__ Ah,
             const __half* __restrict__ Wh,
             const float* __restrict__ bias,
             float* __restrict__ U)
{
    extern __shared__ char smem[];
    const uint32_t sb = smem_to_u32(smem);

    const int tid    = threadIdx.x;
    const int wid    = tid >> 5;
    const int lane   = tid & 31;
    const int group  = lane >> 2;         // 0..7
    const int tid4   = lane & 3;          // 0..3
    const int m_off  = (wid & 3) * 32;    // 4 warps over M=128
    const int n_off  = (wid >> 2) * 64;   // 4 warps over N=256
    const int bn     = blockIdx.x * 256;
    const int bm     = blockIdx.y * 128;
    const bool gate  = (bn >= HID);       // tile never straddles xt/gate split

    // ldmatrix per-lane offsets
    const int a_row = (lane & 7) + ((lane >> 3) & 1) * 8;   // 0..15
    const int a_kb  = ((lane >> 4) & 1) * 8;                // 0 or 8
    const int b_row = (lane & 7) + ((lane >> 4) & 1) * 8;   // n within 16
    const int b_kb  = ((lane >> 3) & 1) * 8;                // 0 or 8

    float acc[2][8][4];
#pragma unroll
    for (int mi = 0; mi < 2; mi++)
#pragma unroll
        for (int ni = 0; ni < 8; ni++)
#pragma unroll
            for (int q = 0; q < 4; q++) acc[mi][ni][q] = 0.f;

    issue_stage(sb + 0 * STAGE_B, Ah, Wh, bm, bn, 0,  tid);
    issue_stage(sb + 1 * STAGE_B, Ah, Wh, bm, bn, BK, tid);

#pragma unroll 1
    for (int s = 0; s < HID / BK; s++) {               // 8 stages
        if (s + 2 < HID / BK) {
            issue_stage(sb + ((s + 2) % NSTAGE) * STAGE_B,
                        Ah, Wh, bm, bn, (s + 2) * BK, tid);
            cp_wait<2>();
        } else if (s + 1 < HID / BK) {
            cp_wait<1>();
        } else {
            cp_wait<0>();
        }
        __syncthreads();

        const uint32_t st = sb + (s % NSTAGE) * STAGE_B;
        const uint32_t sA = st;
        const uint32_t sB = st + A_TILE_B;

#pragma unroll
        for (int kk = 0; kk < BK / 16; kk++) {
            const int kbase = kk * 16;
            uint32_t a_f[2][4];
#pragma unroll
            for (int mi = 0; mi < 2; mi++) {
                uint32_t ao = (uint32_t)((m_off + mi * 16 + a_row) * PITCH_B
                                         + (kbase + a_kb) * 2);
                ldsm_x4(a_f[mi], sA + ao);
            }
            uint32_t b_f[4][4];
#pragma unroll
            for (int nj = 0; nj < 4; nj++) {
                uint32_t bo = (uint32_t)((n_off + nj * 16 + b_row) * PITCH_B
                                         + (kbase + b_kb) * 2);
                ldsm_x4(b_f[nj], sB + bo);
            }
#pragma unroll
            for (int mi = 0; mi < 2; mi++)
#pragma unroll
                for (int ni = 0; ni < 8; ni++) {
                    const int nj = ni >> 1, q = (ni & 1) * 2;
                    mma_fp16(acc[mi][ni], a_f[mi], b_f[nj][q], b_f[nj][q + 1]);
                }
        }
        __syncthreads();
    }

    // ---- epilogue: bias + fast sigmoid on gate cols, float2 stores ----
#pragma unroll
    for (int mi = 0; mi < 2; mi++) {
        const int row0 = bm + m_off + mi * 16 + group;
#pragma unroll
        for (int ni = 0; ni < 8; ni++) {
            const int col = bn + n_off + ni * 8 + tid4 * 2;
            float u0 = acc[mi][ni][0], u1 = acc[mi][ni][1];
            float u2 = acc[mi][ni][2], u3 = acc[mi][ni][3];
            if (gate) {
                const float bz0 = __ldg(&bias[col - HID]);
                const float bz1 = __ldg(&bias[col + 1 - HID]);
                u0 = __fdividef(1.0f, 1.0f + __expf(-(u0 + bz0)));
                u1 = __fdividef(1.0f, 1.0f + __expf(-(u1 + bz1)));
                u2 = __fdividef(1.0f, 1.0f + __expf(-(u2 + bz0)));
                u3 = __fdividef(1.0f, 1.0f + __expf(-(u3 + bz1)));
            }
            *reinterpret_cast<float2*>(&U[(size_t)row0 * NCOLS + col]) =
                make_float2(u0, u1);
            *reinterpret_cast<float2*>(&U[(size_t)(row0 + 8) * NCOLS + col]) =
                make_float2(u2, u3);
        }
    }
}

// ============================================================
// Chunked parallel scan (known-good)
// ============================================================
__global__ void __launch_bounds__(256)
scan_pass1(const float* __restrict__ U, float* __restrict__ P, float* __restrict__ S) {
    int gid  = blockIdx.x * blockDim.x + threadIdx.x;   // 0 .. NCH*BH-1
    int lane = gid & (BH - 1);
    int kc   = gid >> 13;
    int b = lane >> 9, h = lane & (HID - 1);
    int l0 = kc * CHL;

    float c = 0.f, p = 1.f;
    for (int l = l0; l < l0 + CHL; l += SUNROLL) {
        float f[SUNROLL], xt[SUNROLL];
#pragma unroll
        for (int u = 0; u < SUNROLL; u++) {
            const float* up = U + ((size_t)(l + u) * BATCH + b) * NCOLS + h;
            xt[u] = up[0];
            f [u] = up[HID];
        }
#pragma unroll
        for (int u = 0; u < SUNROLL; u++) {
            c = fmaf(f[u], c - xt[u], xt[u]);
            p *= f[u];
        }
    }
    P[(size_t)kc * BH + lane] = p;
    S[(size_t)kc * BH + lane] = c;
}

__global__ void __launch_bounds__(256)
scan_pass2(const float* __restrict__ P, const float* __restrict__ S,
           float* __restrict__ Cin) {
    int lane = blockIdx.x * blockDim.x + threadIdx.x;   // 0..BH-1
    float c = 0.f;
#pragma unroll
    for (int k = 0; k < NCH; k++) {
        Cin[(size_t)k * BH + lane] = c;
        c = fmaf(P[(size_t)k * BH + lane], c, S[(size_t)k * BH + lane]);
    }
}

__global__ void __launch_bounds__(256)
scan_pass3(const float* __restrict__ U, const float* __restrict__ xin,
           const float* __restrict__ Cin, float* __restrict__ hout,
           __half* __restrict__ hfp16) {
    int gid  = blockIdx.x * blockDim.x + threadIdx.x;
    int lane = gid & (BH - 1);
    int kc   = gid >> 13;
    int b = lane >> 9, h = lane & (HID - 1);
    int l0 = kc * CHL;

    float c = Cin[(size_t)kc * BH + lane];
    for (int l = l0; l < l0 + CHL; l += SUNROLL) {
        float f[SUNROLL], xt[SUNROLL], r[SUNROLL], xv[SUNROLL];
#pragma unroll
        for (int u = 0; u < SUNROLL; u++) {
            size_t row = (size_t)(l + u) * BATCH + b;
            const float* up = U + row * NCOLS + h;
            xt[u] = up[0];
            f [u] = up[HID];
            r [u] = up[2 * HID];
            xv[u] = xin[row * HID + h];
        }
#pragma unroll
        for (int u = 0; u < SUNROLL; u++) {
            c = fmaf(f[u], c - xt[u], xt[u]);
            float hv = fmaf(r[u], c - xv[u], xv[u]);
            size_t idx = ((size_t)(l + u) * BATCH + b) * HID + h;
            hout[idx] = hv;
            hfp16[idx] = __float2half_rn(hv);
        }
    }
}

// ============================================================
// Final FC (known-good)
// ============================================================
__global__ void __launch_bounds__(256)
fc_kernel(const float* __restrict__ Hf, const float* __restrict__ fcW,
          const float* __restrict__ fcb, float* __restrict__ out) {
    __shared__ float Wsm[OUT_F * HID];
    int tid = threadIdx.x;
    for (int i = tid; i < OUT_F * HID; i += 256) Wsm[i] = fcW[i];
    __syncthreads();

    int warp = tid >> 5, lane = tid & 31;
    int row = blockIdx.x * 8 + warp;
    const float* hp = Hf + (size_t)row * HID;

    float acc[OUT_F];
#pragma unroll
    for (int n = 0; n < OUT_F; n++) acc[n] = 0.f;

    for (int k = lane; k < HID; k += 32) {
        float xv = hp[k];
#pragma unroll
        for (int n = 0; n < OUT_F; n++)
            acc[n] = fmaf(xv, Wsm[n * HID + k], acc[n]);
    }
#pragma unroll
    for (int n = 0; n < OUT_F; n++) {
        float v = acc[n];
        v += __shfl_xor_sync(0xFFFFFFFFu, v, 16);
        v += __shfl_xor_sync(0xFFFFFFFFu, v, 8);
        v += __shfl_xor_sync(0xFFFFFFFFu, v, 4);
        v += __shfl_xor_sync(0xFFFFFFFFu, v, 2);
        v += __shfl_xor_sync(0xFFFFFFFFu, v, 1);
        if (lane == 0) out[(size_t)row * OUT_F + n] = v + fcb[n];
    }
}

// ============================================================
// Host launcher (graph-capturable: kernel launches only)
// ============================================================
extern "C" void kernel_launch(void* const* d_in, const int* in_sizes, int n_in,
                              void* d_out, int out_size) {
    const float* x    = (const float*)d_in[0];
    const float* Ws   = (const float*)d_in[1];
    const float* bs   = (const float*)d_in[2];
    const float* fcW  = (const float*)d_in[3];
    const float* fcb  = (const float*)d_in[4];
    float* out        = (float*)d_out;

    float *U, *h0, *h1, *P, *S, *Cin;
    __half *Ah, *Wh;
    cudaGetSymbolAddress((void**)&U,   g_U);
    cudaGetSymbolAddress((void**)&h0,  g_h0);
    cudaGetSymbolAddress((void**)&h1,  g_h1);
    cudaGetSymbolAddress((void**)&Ah,  g_Ah);
    cudaGetSymbolAddress((void**)&Wh,  g_Wh);
    cudaGetSymbolAddress((void**)&P,   g_P);
    cudaGetSymbolAddress((void**)&S,   g_S);
    cudaGetSymbolAddress((void**)&Cin, g_Cin);

    cudaFuncSetAttribute(sru_gemm_mma,
                         cudaFuncAttributeMaxDynamicSharedMemorySize, SMEM_GEMM);

    const int nA4   = MROWS * HID / 4;
    const int nWall = NLAY * NCOLS * HID / 4;
    dim3 gm_grid(NCOLS / 256, MROWS / 128);   // (6, 256)
    const int scan_grid = NCH * BH / 256;     // 1024

    // One-time: convert all weights and layer-0 activations to fp16.
    convert_fp16<<<(nWall + 255) / 256, 256>>>(Ws, Wh, nWall);
    convert_fp16<<<(nA4 + 255) / 256, 256>>>(x, Ah, nA4);

    const float* cur = x;
    for (int l = 0; l < NLAY; l++) {
        const size_t woff = (size_t)l * NCOLS * HID;
        sru_gemm_mma<<<gm_grid, 512, SMEM_GEMM>>>(Ah, Wh + woff,
                                                  bs + (size_t)l * (2 * HID), U);
        float* hout = (l & 1) ? h1 : h0;
        scan_pass1<<<scan_grid, 256>>>(U, P, S);
        scan_pass2<<<BH / 256, 256>>>(P, S, Cin);
        scan_pass3<<<scan_grid, 256>>>(U, cur, Cin, hout, Ah);
        cur = hout;
    }
    fc_kernel<<<MROWS / 8, 256>>>(cur, fcW, fcb, out);
}

// round 11
// speedup vs baseline: 5.2607x; 1.0679x over previous
#include <cuda_runtime.h>
#include <cuda_fp16.h>
#include <cstdint>
#include <cstddef>

// Problem constants
#define SEQ   2048
#define BATCH 16
#define HID   512
#define OUT_F 10
#define NLAY  5
#define MROWS (SEQ * BATCH)      // 32768
#define NCOLS (3 * HID)          // 1536
#define BH    (BATCH * HID)      // 8192

// Scan chunking
#define NCH   32
#define CHL   (SEQ / NCH)        // 64 timesteps per chunk
#define SUNROLL 8

// ---------------- device scratch (no allocations allowed) ----------------
__device__ __half g_U [(size_t)MROWS * NCOLS];         // 96 MB: [xt | f | r] fp16
__device__ __half g_A0[(size_t)MROWS * HID];           // 32 MB activations ping
__device__ __half g_A1[(size_t)MROWS * HID];           // 32 MB activations pong
__device__ __half g_Wh[(size_t)NLAY * NCOLS * HID];    // 7.5 MB weights fp16
__device__ float g_P  [(size_t)NCH * BH];              // 1 MB chunk f-products
__device__ float g_S  [(size_t)NCH * BH];              // 1 MB chunk end-states
__device__ float g_Cin[(size_t)NCH * BH];              // 1 MB chunk initial c

// ================= arch-neutral PTX helpers (sm_80+ features only) =======
__device__ __forceinline__ uint32_t smem_to_u32(const void* p) {
    uint32_t a;
    asm("{ .reg .u64 t; cvta.to.shared.u64 t, %1; cvt.u32.u64 %0, t; }"
        : "=r"(a) : "l"(p));
    return a;
}
__device__ __forceinline__ void cp16(uint32_t saddr, const void* g) {
    asm volatile("cp.async.cg.shared.global [%0], [%1], 16;"
                 :: "r"(saddr), "l"(g) : "memory");
}
__device__ __forceinline__ void cp_commit() {
    asm volatile("cp.async.commit_group;" ::: "memory");
}
template <int N>
__device__ __forceinline__ void cp_wait() {
    asm volatile("cp.async.wait_group %0;" :: "n"(N) : "memory");
}
__device__ __forceinline__ void ldsm_x4(uint32_t (&r)[4], uint32_t addr) {
    asm volatile("ldmatrix.sync.aligned.m8n8.x4.shared.b16 {%0,%1,%2,%3}, [%4];"
                 : "=r"(r[0]), "=r"(r[1]), "=r"(r[2]), "=r"(r[3])
                 : "r"(addr));
}
__device__ __forceinline__ void mma_fp16(float (&d)[4], const uint32_t (&a)[4],
                                         uint32_t b0, uint32_t b1) {
    asm volatile(
        "mma.sync.aligned.m16n8k16.row.col.f32.f16.f16.f32 "
        "{%0,%1,%2,%3}, {%4,%5,%6,%7}, {%8,%9}, {%0,%1,%2,%3};"
        : "+f"(d[0]), "+f"(d[1]), "+f"(d[2]), "+f"(d[3])
        : "r"(a[0]), "r"(a[1]), "r"(a[2]), "r"(a[3]), "r"(b0), "r"(b1));
}

// ============================================================
// fp32 -> fp16 convert.  n4 = element_count / 4.
// ============================================================
__global__ void convert_fp16(const float* __restrict__ in,
                             __half* __restrict__ out, int n4) {
    int i = blockIdx.x * blockDim.x + threadIdx.x;
    if (i >= n4) return;
    float4 v = reinterpret_cast<const float4*>(in)[i];
    __half h[4];
    h[0] = __float2half_rn(v.x);  h[1] = __float2half_rn(v.y);
    h[2] = __float2half_rn(v.z);  h[3] = __float2half_rn(v.w);
    reinterpret_cast<uint2*>(out)[i] = *reinterpret_cast<uint2*>(h);
}

// ============================================================
// Tensor-core GEMM via mma.sync (fp16, fp32 accum):
//   U[M=32768, N=1536] = A[M,512] * W[N,512]^T   (U stored fp16)
// CTA tile 128(M) x 256(N), BK=64, 3-stage cp.async pipeline, 512 thr.
// 16 warps: 4(M) x 4(N), warp tile 32 x 64 -> 2 x 8 fragments.
// Epilogue: cols >= 512 -> sigmoid(u + bias[n-512]); half2 stores.
// ============================================================
#define BK 64
#define PITCH_B 144
#define A_TILE_B (128 * PITCH_B)          // 18432 B  (128 x 64 fp16)
#define B_TILE_B (256 * PITCH_B)          // 36864 B  (256 x 64 fp16)
#define STAGE_B (A_TILE_B + B_TILE_B)     // 55296 B
#define NSTAGE 3
#define SMEM_GEMM (NSTAGE * STAGE_B)      // 165888 B

__device__ __forceinline__ void issue_stage(
    uint32_t sbase, const __half* __restrict__ Ah,
    const __half* __restrict__ Wh,
    int bm, int bn, int k0, int tid)
{
    // 3072 16B-chunks per stage / 512 threads = 6 per thread.
#pragma unroll
    for (int i = 0; i < 6; i++) {
        int c = tid + i * 512;
        const __half* src;
        uint32_t toff;
        int row, kc;
        if (i < 2) {                       // A: 128 rows
            int idx = c;
            row = idx >> 3;  kc = idx & 7;
            src  = Ah + (size_t)(bm + row) * HID + k0 + kc * 8;
            toff = 0u;
        } else {                           // W: 256 rows
            int idx = c - 1024;
            row = idx >> 3;  kc = idx & 7;
            src  = Wh + (size_t)(bn + row) * HID + k0 + kc * 8;
            toff = (uint32_t)A_TILE_B;
        }
        cp16(sbase + toff + (uint32_t)(row * PITCH_B + kc * 16), src);
    }
    cp_commit();
}

__global__ void __launch_bounds__(512, 1)
sru_gemm_mma(const __half* __restrict__ Ah,
             const __half* __restrict__ Wh,
             const float* __restrict__ bias,
             __half* __restrict__ U)
{
    extern __shared__ char smem[];
    const uint32_t sb = smem_to_u32(smem);

    const int tid    = threadIdx.x;
    const int wid    = tid >> 5;
    const int lane   = tid & 31;
    const int group  = lane >> 2;         // 0..7
    const int tid4   = lane & 3;          // 0..3
    const int m_off  = (wid & 3) * 32;    // 4 warps over M=128
    const int n_off  = (wid >> 2) * 64;   // 4 warps over N=256
    const int bn     = blockIdx.x * 256;
    const int bm     = blockIdx.y * 128;
    const bool gate  = (bn >= HID);       // tile never straddles xt/gate split

    const int a_row = (lane & 7) + ((lane >> 3) & 1) * 8;
    const int a_kb  = ((lane >> 4) & 1) * 8;
    const int b_row = (lane & 7) + ((lane >> 4) & 1) * 8;
    const int b_kb  = ((lane >> 3) & 1) * 8;

    float acc[2][8][4];
#pragma unroll
    for (int mi = 0; mi < 2; mi++)
#pragma unroll
        for (int ni = 0; ni < 8; ni++)
#pragma unroll
            for (int q = 0; q < 4; q++) acc[mi][ni][q] = 0.f;

    issue_stage(sb + 0 * STAGE_B, Ah, Wh, bm, bn, 0,  tid);
    issue_stage(sb + 1 * STAGE_B, Ah, Wh, bm, bn, BK, tid);

#pragma unroll 1
    for (int s = 0; s < HID / BK; s++) {               // 8 stages
        if (s + 2 < HID / BK) {
            issue_stage(sb + ((s + 2) % NSTAGE) * STAGE_B,
                        Ah, Wh, bm, bn, (s + 2) * BK, tid);
            cp_wait<2>();
        } else if (s + 1 < HID / BK) {
            cp_wait<1>();
        } else {
            cp_wait<0>();
        }
        __syncthreads();

        const uint32_t st = sb + (s % NSTAGE) * STAGE_B;
        const uint32_t sA = st;
        const uint32_t sB = st + A_TILE_B;

#pragma unroll
        for (int kk = 0; kk < BK / 16; kk++) {
            const int kbase = kk * 16;
            uint32_t a_f[2][4];
#pragma unroll
            for (int mi = 0; mi < 2; mi++) {
                uint32_t ao = (uint32_t)((m_off + mi * 16 + a_row) * PITCH_B
                                         + (kbase + a_kb) * 2);
                ldsm_x4(a_f[mi], sA + ao);
            }
            uint32_t b_f[4][4];
#pragma unroll
            for (int nj = 0; nj < 4; nj++) {
                uint32_t bo = (uint32_t)((n_off + nj * 16 + b_row) * PITCH_B
                                         + (kbase + b_kb) * 2);
                ldsm_x4(b_f[nj], sB + bo);
            }
#pragma unroll
            for (int mi = 0; mi < 2; mi++)
#pragma unroll
                for (int ni = 0; ni < 8; ni++) {
                    const int nj = ni >> 1, q = (ni & 1) * 2;
                    mma_fp16(acc[mi][ni], a_f[mi], b_f[nj][q], b_f[nj][q + 1]);
                }
        }
        __syncthreads();
    }

    // ---- epilogue: bias + fast sigmoid on gate cols, half2 stores ----
#pragma unroll
    for (int mi = 0; mi < 2; mi++) {
        const int row0 = bm + m_off + mi * 16 + group;
#pragma unroll
        for (int ni = 0; ni < 8; ni++) {
            const int col = bn + n_off + ni * 8 + tid4 * 2;
            float u0 = acc[mi][ni][0], u1 = acc[mi][ni][1];
            float u2 = acc[mi][ni][2], u3 = acc[mi][ni][3];
            if (gate) {
                const float bz0 = __ldg(&bias[col - HID]);
                const float bz1 = __ldg(&bias[col + 1 - HID]);
                u0 = __fdividef(1.0f, 1.0f + __expf(-(u0 + bz0)));
                u1 = __fdividef(1.0f, 1.0f + __expf(-(u1 + bz1)));
                u2 = __fdividef(1.0f, 1.0f + __expf(-(u2 + bz0)));
                u3 = __fdividef(1.0f, 1.0f + __expf(-(u3 + bz1)));
            }
            *reinterpret_cast<__half2*>(&U[(size_t)row0 * NCOLS + col]) =
                __floats2half2_rn(u0, u1);
            *reinterpret_cast<__half2*>(&U[(size_t)(row0 + 8) * NCOLS + col]) =
                __floats2half2_rn(u2, u3);
        }
    }
}

// ============================================================
// Chunked parallel scan over fp16 U (fp32 arithmetic).
// ============================================================
__global__ void __launch_bounds__(256)
scan_pass1(const __half* __restrict__ U, float* __restrict__ P, float* __restrict__ S) {
    int gid  = blockIdx.x * blockDim.x + threadIdx.x;   // 0 .. NCH*BH-1
    int lane = gid & (BH - 1);
    int kc   = gid >> 13;
    int b = lane >> 9, h = lane & (HID - 1);
    int l0 = kc * CHL;

    float c = 0.f, p = 1.f;
    for (int l = l0; l < l0 + CHL; l += SUNROLL) {
        float f[SUNROLL], xt[SUNROLL];
#pragma unroll
        for (int u = 0; u < SUNROLL; u++) {
            const __half* up = U + ((size_t)(l + u) * BATCH + b) * NCOLS + h;
            xt[u] = __half2float(up[0]);
            f [u] = __half2float(up[HID]);
        }
#pragma unroll
        for (int u = 0; u < SUNROLL; u++) {
            c = fmaf(f[u], c - xt[u], xt[u]);
            p *= f[u];
        }
    }
    P[(size_t)kc * BH + lane] = p;
    S[(size_t)kc * BH + lane] = c;
}

__global__ void __launch_bounds__(256)
scan_pass2(const float* __restrict__ P, const float* __restrict__ S,
           float* __restrict__ Cin) {
    int lane = blockIdx.x * blockDim.x + threadIdx.x;   // 0..BH-1
    float c = 0.f;
#pragma unroll
    for (int k = 0; k < NCH; k++) {
        Cin[(size_t)k * BH + lane] = c;
        c = fmaf(P[(size_t)k * BH + lane], c, S[(size_t)k * BH + lane]);
    }
}

__global__ void __launch_bounds__(256)
scan_pass3(const __half* __restrict__ U, const __half* __restrict__ xin,
           const float* __restrict__ Cin, __half* __restrict__ hout) {
    int gid  = blockIdx.x * blockDim.x + threadIdx.x;
    int lane = gid & (BH - 1);
    int kc   = gid >> 13;
    int b = lane >> 9, h = lane & (HID - 1);
    int l0 = kc * CHL;

    float c = Cin[(size_t)kc * BH + lane];
    for (int l = l0; l < l0 + CHL; l += SUNROLL) {
        float f[SUNROLL], xt[SUNROLL], r[SUNROLL], xv[SUNROLL];
#pragma unroll
        for (int u = 0; u < SUNROLL; u++) {
            size_t row = (size_t)(l + u) * BATCH + b;
            const __half* up = U + row * NCOLS + h;
            xt[u] = __half2float(up[0]);
            f [u] = __half2float(up[HID]);
            r [u] = __half2float(up[2 * HID]);
            xv[u] = __half2float(xin[row * HID + h]);
        }
#pragma unroll
        for (int u = 0; u < SUNROLL; u++) {
            c = fmaf(f[u], c - xt[u], xt[u]);
            float hv = fmaf(r[u], c - xv[u], xv[u]);
            hout[((size_t)(l + u) * BATCH + b) * HID + h] = __float2half_rn(hv);
        }
    }
}

// ============================================================
// Final FC (fp16 activations, fp32 weights/accum)
// ============================================================
__global__ void __launch_bounds__(256)
fc_kernel(const __half* __restrict__ Hf, const float* __restrict__ fcW,
          const float* __restrict__ fcb, float* __restrict__ out) {
    __shared__ float Wsm[OUT_F * HID];
    int tid = threadIdx.x;
    for (int i = tid; i < OUT_F * HID; i += 256) Wsm[i] = fcW[i];
    __syncthreads();

    int warp = tid >> 5, lane = tid & 31;
    int row = blockIdx.x * 8 + warp;
    const __half* hp = Hf + (size_t)row * HID;

    float acc[OUT_F];
#pragma unroll
    for (int n = 0; n < OUT_F; n++) acc[n] = 0.f;

    for (int k = lane; k < HID; k += 32) {
        float xv = __half2float(hp[k]);
#pragma unroll
        for (int n = 0; n < OUT_F; n++)
            acc[n] = fmaf(xv, Wsm[n * HID + k], acc[n]);
    }
#pragma unroll
    for (int n = 0; n < OUT_F; n++) {
        float v = acc[n];
        v += __shfl_xor_sync(0xFFFFFFFFu, v, 16);
        v += __shfl_xor_sync(0xFFFFFFFFu, v, 8);
        v += __shfl_xor_sync(0xFFFFFFFFu, v, 4);
        v += __shfl_xor_sync(0xFFFFFFFFu, v, 2);
        v += __shfl_xor_sync(0xFFFFFFFFu, v, 1);
        if (lane == 0) out[(size_t)row * OUT_F + n] = v + fcb[n];
    }
}

// ============================================================
// Host launcher (graph-capturable: kernel launches only)
// ============================================================
extern "C" void kernel_launch(void* const* d_in, const int* in_sizes, int n_in,
                              void* d_out, int out_size) {
    const float* x    = (const float*)d_in[0];
    const float* Ws   = (const float*)d_in[1];
    const float* bs   = (const float*)d_in[2];
    const float* fcW  = (const float*)d_in[3];
    const float* fcb  = (const float*)d_in[4];
    float* out        = (float*)d_out;

    float *P, *S, *Cin;
    __half *U, *A0, *A1, *Wh;
    cudaGetSymbolAddress((void**)&U,   g_U);
    cudaGetSymbolAddress((void**)&A0,  g_A0);
    cudaGetSymbolAddress((void**)&A1,  g_A1);
    cudaGetSymbolAddress((void**)&Wh,  g_Wh);
    cudaGetSymbolAddress((void**)&P,   g_P);
    cudaGetSymbolAddress((void**)&S,   g_S);
    cudaGetSymbolAddress((void**)&Cin, g_Cin);

    cudaFuncSetAttribute(sru_gemm_mma,
                         cudaFuncAttributeMaxDynamicSharedMemorySize, SMEM_GEMM);

    const int nA4   = MROWS * HID / 4;
    const int nWall = NLAY * NCOLS * HID / 4;
    dim3 gm_grid(NCOLS / 256, MROWS / 128);   // (6, 256)
    const int scan_grid = NCH * BH / 256;     // 1024

    // One-time: convert all weights and layer-0 activations to fp16.
    convert_fp16<<<(nWall + 255) / 256, 256>>>(Ws, Wh, nWall);
    convert_fp16<<<(nA4 + 255) / 256, 256>>>(x, A0, nA4);

    __half* cur = A0;
    __half* nxt = A1;
    for (int l = 0; l < NLAY; l++) {
        const size_t woff = (size_t)l * NCOLS * HID;
        sru_gemm_mma<<<gm_grid, 512, SMEM_GEMM>>>(cur, Wh + woff,
                                                  bs + (size_t)l * (2 * HID), U);
        scan_pass1<<<scan_grid, 256>>>(U, P, S);
        scan_pass2<<<BH / 256, 256>>>(P, S, Cin);
        scan_pass3<<<scan_grid, 256>>>(U, cur, Cin, nxt);
        __half* t = cur; cur = nxt; nxt = t;
    }
    fc_kernel<<<MROWS / 8, 256>>>(cur, fcW, fcb, out);
}

// round 12
// speedup vs baseline: 5.6096x; 1.0663x over previous
#include <cuda_runtime.h>
#include <cuda_fp16.h>
#include <cstdint>
#include <cstddef>

// Problem constants
#define SEQ   2048
#define BATCH 16
#define HID   512
#define OUT_F 10
#define NLAY  5
#define MROWS (SEQ * BATCH)      // 32768
#define NCOLS (3 * HID)          // 1536
#define BH    (BATCH * HID)      // 8192
#define BH2   (BH / 2)           // 4096

// Scan chunking
#define NCH   32
#define CHL   (SEQ / NCH)        // 64 timesteps per chunk
#define SUNROLL 8

// ---------------- device scratch (no allocations allowed) ----------------
__device__ __half g_U [(size_t)MROWS * NCOLS];         // 96 MB: [xt | f | r] fp16
__device__ __half g_A0[(size_t)MROWS * HID];           // 32 MB activations ping
__device__ __half g_A1[(size_t)MROWS * HID];           // 32 MB activations pong
__device__ __half g_Wh[(size_t)NLAY * NCOLS * HID];    // 7.5 MB weights fp16
__device__ float g_P  [(size_t)NCH * BH];              // 1 MB chunk f-products
__device__ float g_S  [(size_t)NCH * BH];              // 1 MB chunk end-states
__device__ float g_Cin[(size_t)NCH * BH];              // 1 MB chunk initial c

// ================= arch-neutral PTX helpers (sm_80+ features only) =======
__device__ __forceinline__ uint32_t smem_to_u32(const void* p) {
    uint32_t a;
    asm("{ .reg .u64 t; cvta.to.shared.u64 t, %1; cvt.u32.u64 %0, t; }"
        : "=r"(a) : "l"(p));
    return a;
}
__device__ __forceinline__ void cp16(uint32_t saddr, const void* g) {
    asm volatile("cp.async.cg.shared.global [%0], [%1], 16;"
                 :: "r"(saddr), "l"(g) : "memory");
}
__device__ __forceinline__ void cp_commit() {
    asm volatile("cp.async.commit_group;" ::: "memory");
}
template <int N>
__device__ __forceinline__ void cp_wait() {
    asm volatile("cp.async.wait_group %0;" :: "n"(N) : "memory");
}
__device__ __forceinline__ void ldsm_x4(uint32_t (&r)[4], uint32_t addr) {
    asm volatile("ldmatrix.sync.aligned.m8n8.x4.shared.b16 {%0,%1,%2,%3}, [%4];"
                 : "=r"(r[0]), "=r"(r[1]), "=r"(r[2]), "=r"(r[3])
                 : "r"(addr));
}
__device__ __forceinline__ void mma_fp16(float (&d)[4], const uint32_t (&a)[4],
                                         uint32_t b0, uint32_t b1) {
    asm volatile(
        "mma.sync.aligned.m16n8k16.row.col.f32.f16.f16.f32 "
        "{%0,%1,%2,%3}, {%4,%5,%6,%7}, {%8,%9}, {%0,%1,%2,%3};"
        : "+f"(d[0]), "+f"(d[1]), "+f"(d[2]), "+f"(d[3])
        : "r"(a[0]), "r"(a[1]), "r"(a[2]), "r"(a[3]), "r"(b0), "r"(b1));
}

// ============================================================
// fp32 -> fp16 convert.  n4 = element_count / 4.
// ============================================================
__global__ void convert_fp16(const float* __restrict__ in,
                             __half* __restrict__ out, int n4) {
    int i = blockIdx.x * blockDim.x + threadIdx.x;
    if (i >= n4) return;
    float4 v = reinterpret_cast<const float4*>(in)[i];
    __half h[4];
    h[0] = __float2half_rn(v.x);  h[1] = __float2half_rn(v.y);
    h[2] = __float2half_rn(v.z);  h[3] = __float2half_rn(v.w);
    reinterpret_cast<uint2*>(out)[i] = *reinterpret_cast<uint2*>(h);
}

// ============================================================
// Persistent tensor-core GEMM via mma.sync (fp16, fp32 accum):
//   U[M=32768, N=1536] = A[M,512] * W[N,512]^T   (U stored fp16)
// Grid = GPERS persistent CTAs; each walks tiles bid, bid+G, ...
// CTA tile 128(M) x 256(N), BK=64, 3-buffer cp.async ring that is
// pipelined ACROSS tiles (never drains); ONE __syncthreads per stage.
// 16 warps: 4(M) x 4(N), warp tile 32 x 64.
// Epilogue: cols >= 512 -> sigmoid(u + bias[n-512]); half2 stores.
// ============================================================
#define BK 64
#define PITCH_B 144
#define A_TILE_B (128 * PITCH_B)          // 18432 B
#define B_TILE_B (256 * PITCH_B)          // 36864 B
#define STAGE_B (A_TILE_B + B_TILE_B)     // 55296 B
#define NSTAGE 3
#define SMEM_GEMM (NSTAGE * STAGE_B)      // 165888 B
#define NTILE_N 6                         // 1536 / 256
#define NTILE   (NTILE_N * (MROWS / 128)) // 1536 tiles
#define KST     8                         // K-stages per tile (512/64)
#define GPERS   148                       // persistent CTAs

__device__ __forceinline__ void issue_stage_g(
    uint32_t sb, const __half* __restrict__ Ah,
    const __half* __restrict__ Wh,
    int bid, int g, int tid)
{
    const int i    = g >> 3;
    const int s    = g & 7;
    const int tile = bid + i * GPERS;
    const int bn   = (tile % NTILE_N) * 256;
    const int bm   = (tile / NTILE_N) * 128;
    const int k0   = s * BK;
    const uint32_t sbase = sb + (uint32_t)(g % NSTAGE) * STAGE_B;
    // 3072 16B-chunks per stage / 512 threads = 6 per thread.
#pragma unroll
    for (int q = 0; q < 6; q++) {
        int c = tid + q * 512;
        const __half* src;
        uint32_t toff;
        int row, kc;
        if (q < 2) {                       // A: 128 rows
            row = c >> 3;  kc = c & 7;
            src  = Ah + (size_t)(bm + row) * HID + k0 + kc * 8;
            toff = 0u;
        } else {                           // W: 256 rows
            int idx = c - 1024;
            row = idx >> 3;  kc = idx & 7;
            src  = Wh + (size_t)(bn + row) * HID + k0 + kc * 8;
            toff = (uint32_t)A_TILE_B;
        }
        cp16(sbase + toff + (uint32_t)(row * PITCH_B + kc * 16), src);
    }
    cp_commit();
}

__global__ void __launch_bounds__(512, 1)
sru_gemm_mma(const __half* __restrict__ Ah,
             const __half* __restrict__ Wh,
             const float* __restrict__ bias,
             __half* __restrict__ U)
{
    extern __shared__ char smem[];
    const uint32_t sb = smem_to_u32(smem);

    const int tid    = threadIdx.x;
    const int bid    = blockIdx.x;
    const int wid    = tid >> 5;
    const int lane   = tid & 31;
    const int group  = lane >> 2;
    const int tid4   = lane & 3;
    const int m_off  = (wid & 3) * 32;
    const int n_off  = (wid >> 2) * 64;

    const int a_row = (lane & 7) + ((lane >> 3) & 1) * 8;
    const int a_kb  = ((lane >> 4) & 1) * 8;
    const int b_row = (lane & 7) + ((lane >> 4) & 1) * 8;
    const int b_kb  = ((lane >> 3) & 1) * 8;

    const int nt = (bid < NTILE) ? ((NTILE - 1 - bid) / GPERS + 1) : 0;
    const int T  = nt * KST;
    if (T == 0) return;

    float acc[2][8][4];
#pragma unroll
    for (int mi = 0; mi < 2; mi++)
#pragma unroll
        for (int ni = 0; ni < 8; ni++)
#pragma unroll
            for (int q = 0; q < 4; q++) acc[mi][ni][q] = 0.f;

    issue_stage_g(sb, Ah, Wh, bid, 0, tid);
    if (T > 1) issue_stage_g(sb, Ah, Wh, bid, 1, tid);

#pragma unroll 1
    for (int g = 0; g < T; g++) {
        if (g == T - 1) cp_wait<0>(); else cp_wait<1>();
        __syncthreads();                       // one sync per stage
        if (g + 2 < T) issue_stage_g(sb, Ah, Wh, bid, g + 2, tid);

        const uint32_t st = sb + (uint32_t)(g % NSTAGE) * STAGE_B;
        const uint32_t sA = st;
        const uint32_t sB = st + A_TILE_B;

#pragma unroll
        for (int kk = 0; kk < BK / 16; kk++) {
            const int kbase = kk * 16;
            uint32_t a_f[2][4];
#pragma unroll
            for (int mi = 0; mi < 2; mi++) {
                uint32_t ao = (uint32_t)((m_off + mi * 16 + a_row) * PITCH_B
                                         + (kbase + a_kb) * 2);
                ldsm_x4(a_f[mi], sA + ao);
            }
            uint32_t b_f[4][4];
#pragma unroll
            for (int nj = 0; nj < 4; nj++) {
                uint32_t bo = (uint32_t)((n_off + nj * 16 + b_row) * PITCH_B
                                         + (kbase + b_kb) * 2);
                ldsm_x4(b_f[nj], sB + bo);
            }
#pragma unroll
            for (int mi = 0; mi < 2; mi++)
#pragma unroll
                for (int ni = 0; ni < 8; ni++) {
                    const int nj = ni >> 1, q = (ni & 1) * 2;
                    mma_fp16(acc[mi][ni], a_f[mi], b_f[nj][q], b_f[nj][q + 1]);
                }
        }

        if ((g & 7) == 7) {
            // ---- epilogue for tile g/8 (overlaps next tile's loads) ----
            const int tile = bid + (g >> 3) * GPERS;
            const int bn   = (tile % NTILE_N) * 256;
            const int bm   = (tile / NTILE_N) * 128;
            const bool gate = (bn >= HID);
#pragma unroll
            for (int mi = 0; mi < 2; mi++) {
                const int row0 = bm + m_off + mi * 16 + group;
#pragma unroll
                for (int ni = 0; ni < 8; ni++) {
                    const int col = bn + n_off + ni * 8 + tid4 * 2;
                    float u0 = acc[mi][ni][0], u1 = acc[mi][ni][1];
                    float u2 = acc[mi][ni][2], u3 = acc[mi][ni][3];
                    if (gate) {
                        const float bz0 = __ldg(&bias[col - HID]);
                        const float bz1 = __ldg(&bias[col + 1 - HID]);
                        u0 = __fdividef(1.0f, 1.0f + __expf(-(u0 + bz0)));
                        u1 = __fdividef(1.0f, 1.0f + __expf(-(u1 + bz1)));
                        u2 = __fdividef(1.0f, 1.0f + __expf(-(u2 + bz0)));
                        u3 = __fdividef(1.0f, 1.0f + __expf(-(u3 + bz1)));
                    }
                    *reinterpret_cast<__half2*>(&U[(size_t)row0 * NCOLS + col]) =
                        __floats2half2_rn(u0, u1);
                    *reinterpret_cast<__half2*>(&U[(size_t)(row0 + 8) * NCOLS + col]) =
                        __floats2half2_rn(u2, u3);
                    acc[mi][ni][0] = 0.f; acc[mi][ni][1] = 0.f;
                    acc[mi][ni][2] = 0.f; acc[mi][ni][3] = 0.f;
                }
            }
        }
    }
}

// ============================================================
// Chunked parallel scan, half2 lanes (2 adjacent h per thread).
// ============================================================
__global__ void __launch_bounds__(256)
scan_pass1(const __half* __restrict__ U, float* __restrict__ P, float* __restrict__ S) {
    int gid   = blockIdx.x * blockDim.x + threadIdx.x;   // 0 .. NCH*BH2-1
    int lane2 = gid & (BH2 - 1);
    int kc    = gid >> 12;                               // BH2 = 4096
    int b  = lane2 >> 8;                                 // HID/2 = 256
    int h2 = lane2 & 255;
    int l0 = kc * CHL;
    const __half2* U2 = reinterpret_cast<const __half2*>(U);

    float c0 = 0.f, c1 = 0.f, p0 = 1.f, p1 = 1.f;
    for (int l = l0; l < l0 + CHL; l += SUNROLL) {
        float2 f[SUNROLL], xt[SUNROLL];
#pragma unroll
        for (int u = 0; u < SUNROLL; u++) {
            size_t base = ((size_t)(l + u) * BATCH + b) * (NCOLS / 2) + h2;
            xt[u] = __half22float2(U2[base]);
            f [u] = __half22float2(U2[base + HID / 2]);
        }
#pragma unroll
        for (int u = 0; u < SUNROLL; u++) {
            c0 = fmaf(f[u].x, c0 - xt[u].x, xt[u].x);
            c1 = fmaf(f[u].y, c1 - xt[u].y, xt[u].y);
            p0 *= f[u].x;
            p1 *= f[u].y;
        }
    }
    size_t o2 = (size_t)kc * BH2 + lane2;
    reinterpret_cast<float2*>(P)[o2] = make_float2(p0, p1);
    reinterpret_cast<float2*>(S)[o2] = make_float2(c0, c1);
}

__global__ void __launch_bounds__(256)
scan_pass2(const float* __restrict__ P, const float* __restrict__ S,
           float* __restrict__ Cin) {
    int lane = blockIdx.x * blockDim.x + threadIdx.x;   // 0..BH-1
    float c = 0.f;
#pragma unroll
    for (int k = 0; k < NCH; k++) {
        Cin[(size_t)k * BH + lane] = c;
        c = fmaf(P[(size_t)k * BH + lane], c, S[(size_t)k * BH + lane]);
    }
}

__global__ void __launch_bounds__(256)
scan_pass3(const __half* __restrict__ U, const __half* __restrict__ xin,
           const float* __restrict__ Cin, __half* __restrict__ hout) {
    int gid   = blockIdx.x * blockDim.x + threadIdx.x;
    int lane2 = gid & (BH2 - 1);
    int kc    = gid >> 12;
    int b  = lane2 >> 8;
    int h2 = lane2 & 255;
    int l0 = kc * CHL;
    const __half2* U2 = reinterpret_cast<const __half2*>(U);
    const __half2* X2 = reinterpret_cast<const __half2*>(xin);
    __half2* H2 = reinterpret_cast<__half2*>(hout);

    float2 cin = reinterpret_cast<const float2*>(Cin)[(size_t)kc * BH2 + lane2];
    float c0 = cin.x, c1 = cin.y;
    for (int l = l0; l < l0 + CHL; l += SUNROLL) {
        float2 f[SUNROLL], xt[SUNROLL], r[SUNROLL], xv[SUNROLL];
#pragma unroll
        for (int u = 0; u < SUNROLL; u++) {
            size_t row  = (size_t)(l + u) * BATCH + b;
            size_t base = row * (NCOLS / 2) + h2;
            xt[u] = __half22float2(U2[base]);
            f [u] = __half22float2(U2[base + HID / 2]);
            r [u] = __half22float2(U2[base + HID]);
            xv[u] = __half22float2(X2[row * (HID / 2) + h2]);
        }
#pragma unroll
        for (int u = 0; u < SUNROLL; u++) {
            c0 = fmaf(f[u].x, c0 - xt[u].x, xt[u].x);
            c1 = fmaf(f[u].y, c1 - xt[u].y, xt[u].y);
            float h0 = fmaf(r[u].x, c0 - xv[u].x, xv[u].x);
            float h1 = fmaf(r[u].y, c1 - xv[u].y, xv[u].y);
            size_t row = (size_t)(l + u) * BATCH + b;
            H2[row * (HID / 2) + h2] = __floats2half2_rn(h0, h1);
        }
    }
}

// ============================================================
// Final FC (half2 activation reads, fp32 weights/accum)
// ============================================================
__global__ void __launch_bounds__(256)
fc_kernel(const __half* __restrict__ Hf, const float* __restrict__ fcW,
          const float* __restrict__ fcb, float* __restrict__ out) {
    __shared__ float Wsm[OUT_F * HID];
    int tid = threadIdx.x;
    for (int i = tid; i < OUT_F * HID; i += 256) Wsm[i] = fcW[i];
    __syncthreads();

    int warp = tid >> 5, lane = tid & 31;
    int row = blockIdx.x * 8 + warp;
    const __half2* hp = reinterpret_cast<const __half2*>(Hf + (size_t)row * HID);

    float acc[OUT_F];
#pragma unroll
    for (int n = 0; n < OUT_F; n++) acc[n] = 0.f;

    for (int k2 = lane; k2 < HID / 2; k2 += 32) {
        float2 xv = __half22float2(hp[k2]);
#pragma unroll
        for (int n = 0; n < OUT_F; n++) {
            acc[n] = fmaf(xv.x, Wsm[n * HID + 2 * k2],     acc[n]);
            acc[n] = fmaf(xv.y, Wsm[n * HID + 2 * k2 + 1], acc[n]);
        }
    }
#pragma unroll
    for (int n = 0; n < OUT_F; n++) {
        float v = acc[n];
        v += __shfl_xor_sync(0xFFFFFFFFu, v, 16);
        v += __shfl_xor_sync(0xFFFFFFFFu, v, 8);
        v += __shfl_xor_sync(0xFFFFFFFFu, v, 4);
        v += __shfl_xor_sync(0xFFFFFFFFu, v, 2);
        v += __shfl_xor_sync(0xFFFFFFFFu, v, 1);
        if (lane == 0) out[(size_t)row * OUT_F + n] = v + fcb[n];
    }
}

// ============================================================
// Host launcher (graph-capturable: kernel launches only)
// ============================================================
extern "C" void kernel_launch(void* const* d_in, const int* in_sizes, int n_in,
                              void* d_out, int out_size) {
    const float* x    = (const float*)d_in[0];
    const float* Ws   = (const float*)d_in[1];
    const float* bs   = (const float*)d_in[2];
    const float* fcW  = (const float*)d_in[3];
    const float* fcb  = (const float*)d_in[4];
    float* out        = (float*)d_out;

    float *P, *S, *Cin;
    __half *U, *A0, *A1, *Wh;
    cudaGetSymbolAddress((void**)&U,   g_U);
    cudaGetSymbolAddress((void**)&A0,  g_A0);
    cudaGetSymbolAddress((void**)&A1,  g_A1);
    cudaGetSymbolAddress((void**)&Wh,  g_Wh);
    cudaGetSymbolAddress((void**)&P,   g_P);
    cudaGetSymbolAddress((void**)&S,   g_S);
    cudaGetSymbolAddress((void**)&Cin, g_Cin);

    cudaFuncSetAttribute(sru_gemm_mma,
                         cudaFuncAttributeMaxDynamicSharedMemorySize, SMEM_GEMM);

    const int nA4   = MROWS * HID / 4;
    const int nWall = NLAY * NCOLS * HID / 4;
    const int scan_grid = NCH * BH2 / 256;    // 512

    // One-time: convert all weights and layer-0 activations to fp16.
    convert_fp16<<<(nWall + 255) / 256, 256>>>(Ws, Wh, nWall);
    convert_fp16<<<(nA4 + 255) / 256, 256>>>(x, A0, nA4);

    __half* cur = A0;
    __half* nxt = A1;
    for (int l = 0; l < NLAY; l++) {
        const size_t woff = (size_t)l * NCOLS * HID;
        sru_gemm_mma<<<GPERS, 512, SMEM_GEMM>>>(cur, Wh + woff,
                                                bs + (size_t)l * (2 * HID), U);
        scan_pass1<<<scan_grid, 256>>>(U, P, S);
        scan_pass2<<<BH / 256, 256>>>(P, S, Cin);
        scan_pass3<<<scan_grid, 256>>>(U, cur, Cin, nxt);
        __half* t = cur; cur = nxt; nxt = t;
    }
    fc_kernel<<<MROWS / 8, 256>>>(cur, fcW, fcb, out);
}

// round 13
// speedup vs baseline: 5.7130x; 1.0184x over previous
#include <cuda_runtime.h>
#include <cuda_fp16.h>
#include <cstdint>
#include <cstddef>

// Problem constants
#define SEQ   2048
#define BATCH 16
#define HID   512
#define OUT_F 10
#define NLAY  5
#define MROWS (SEQ * BATCH)      // 32768
#define NCOLS (3 * HID)          // 1536
#define BH    (BATCH * HID)      // 8192
#define BH2   (BH / 2)           // 4096

// Scan chunking (64 chunks x 32 steps: grid stays wide at half2 lanes)
#define NCH   64
#define CHL   (SEQ / NCH)        // 32 timesteps per chunk
#define SUNROLL 8

// ---------------- device scratch (no allocations allowed) ----------------
__device__ __half g_U [(size_t)MROWS * NCOLS];         // 96 MB: [xt | f | r] fp16
__device__ __half g_A0[(size_t)MROWS * HID];           // 32 MB activations ping
__device__ __half g_A1[(size_t)MROWS * HID];           // 32 MB activations pong
__device__ __half g_Wh[(size_t)NLAY * NCOLS * HID];    // 7.5 MB weights fp16
__device__ float g_P  [(size_t)NCH * BH];              // 2 MB chunk f-products
__device__ float g_S  [(size_t)NCH * BH];              // 2 MB chunk end-states
__device__ float g_Cin[(size_t)NCH * BH];              // 2 MB chunk initial c

// ================= arch-neutral PTX helpers (sm_80+ features only) =======
__device__ __forceinline__ uint32_t smem_to_u32(const void* p) {
    uint32_t a;
    asm("{ .reg .u64 t; cvta.to.shared.u64 t, %1; cvt.u32.u64 %0, t; }"
        : "=r"(a) : "l"(p));
    return a;
}
__device__ __forceinline__ void cp16(uint32_t saddr, const void* g) {
    asm volatile("cp.async.cg.shared.global [%0], [%1], 16;"
                 :: "r"(saddr), "l"(g) : "memory");
}
__device__ __forceinline__ void cp_commit() {
    asm volatile("cp.async.commit_group;" ::: "memory");
}
template <int N>
__device__ __forceinline__ void cp_wait() {
    asm volatile("cp.async.wait_group %0;" :: "n"(N) : "memory");
}
__device__ __forceinline__ void ldsm_x4(uint32_t (&r)[4], uint32_t addr) {
    asm volatile("ldmatrix.sync.aligned.m8n8.x4.shared.b16 {%0,%1,%2,%3}, [%4];"
                 : "=r"(r[0]), "=r"(r[1]), "=r"(r[2]), "=r"(r[3])
                 : "r"(addr));
}
__device__ __forceinline__ void mma_fp16(float (&d)[4], const uint32_t (&a)[4],
                                         uint32_t b0, uint32_t b1) {
    asm volatile(
        "mma.sync.aligned.m16n8k16.row.col.f32.f16.f16.f32 "
        "{%0,%1,%2,%3}, {%4,%5,%6,%7}, {%8,%9}, {%0,%1,%2,%3};"
        : "+f"(d[0]), "+f"(d[1]), "+f"(d[2]), "+f"(d[3])
        : "r"(a[0]), "r"(a[1]), "r"(a[2]), "r"(a[3]), "r"(b0), "r"(b1));
}

// ============================================================
// fp32 -> fp16 convert.  n4 = element_count / 4.
// ============================================================
__global__ void convert_fp16(const float* __restrict__ in,
                             __half* __restrict__ out, int n4) {
    int i = blockIdx.x * blockDim.x + threadIdx.x;
    if (i >= n4) return;
    float4 v = reinterpret_cast<const float4*>(in)[i];
    __half h[4];
    h[0] = __float2half_rn(v.x);  h[1] = __float2half_rn(v.y);
    h[2] = __float2half_rn(v.z);  h[3] = __float2half_rn(v.w);
    reinterpret_cast<uint2*>(out)[i] = *reinterpret_cast<uint2*>(h);
}

// ============================================================
// Persistent tensor-core GEMM via mma.sync (fp16, fp32 accum):
//   U[M=32768, N=1536] = A[M,512] * W[N,512]^T   (U stored fp16)
// Grid = GPERS persistent CTAs; cross-tile cp.async ring, one sync/stage.
// CTA tile 128(M) x 256(N), BK=64, 16 warps (4x4), warp tile 32x64.
// Epilogue: cols >= 512 -> sigmoid(u + bias[n-512]); half2 stores.
// ============================================================
#define BK 64
#define PITCH_B 144
#define A_TILE_B (128 * PITCH_B)          // 18432 B
#define B_TILE_B (256 * PITCH_B)          // 36864 B
#define STAGE_B (A_TILE_B + B_TILE_B)     // 55296 B
#define NSTAGE 3
#define SMEM_GEMM (NSTAGE * STAGE_B)      // 165888 B
#define NTILE_N 6                         // 1536 / 256
#define NTILE   (NTILE_N * (MROWS / 128)) // 1536 tiles
#define KST     8                         // K-stages per tile (512/64)
#define GPERS   148                       // persistent CTAs

__device__ __forceinline__ void issue_stage_g(
    uint32_t sb, const __half* __restrict__ Ah,
    const __half* __restrict__ Wh,
    int bid, int g, int tid)
{
    const int i    = g >> 3;
    const int s    = g & 7;
    const int tile = bid + i * GPERS;
    const int bn   = (tile % NTILE_N) * 256;
    const int bm   = (tile / NTILE_N) * 128;
    const int k0   = s * BK;
    const uint32_t sbase = sb + (uint32_t)(g % NSTAGE) * STAGE_B;
#pragma unroll
    for (int q = 0; q < 6; q++) {
        int c = tid + q * 512;
        const __half* src;
        uint32_t toff;
        int row, kc;
        if (q < 2) {                       // A: 128 rows
            row = c >> 3;  kc = c & 7;
            src  = Ah + (size_t)(bm + row) * HID + k0 + kc * 8;
            toff = 0u;
        } else {                           // W: 256 rows
            int idx = c - 1024;
            row = idx >> 3;  kc = idx & 7;
            src  = Wh + (size_t)(bn + row) * HID + k0 + kc * 8;
            toff = (uint32_t)A_TILE_B;
        }
        cp16(sbase + toff + (uint32_t)(row * PITCH_B + kc * 16), src);
    }
    cp_commit();
}

__global__ void __launch_bounds__(512, 1)
sru_gemm_mma(const __half* __restrict__ Ah,
             const __half* __restrict__ Wh,
             const float* __restrict__ bias,
             __half* __restrict__ U)
{
    extern __shared__ char smem[];
    const uint32_t sb = smem_to_u32(smem);

    const int tid    = threadIdx.x;
    const int bid    = blockIdx.x;
    const int wid    = tid >> 5;
    const int lane   = tid & 31;
    const int group  = lane >> 2;
    const int tid4   = lane & 3;
    const int m_off  = (wid & 3) * 32;
    const int n_off  = (wid >> 2) * 64;

    const int a_row = (lane & 7) + ((lane >> 3) & 1) * 8;
    const int a_kb  = ((lane >> 4) & 1) * 8;
    const int b_row = (lane & 7) + ((lane >> 4) & 1) * 8;
    const int b_kb  = ((lane >> 3) & 1) * 8;

    const int nt = (bid < NTILE) ? ((NTILE - 1 - bid) / GPERS + 1) : 0;
    const int T  = nt * KST;
    if (T == 0) return;

    float acc[2][8][4];
#pragma unroll
    for (int mi = 0; mi < 2; mi++)
#pragma unroll
        for (int ni = 0; ni < 8; ni++)
#pragma unroll
            for (int q = 0; q < 4; q++) acc[mi][ni][q] = 0.f;

    issue_stage_g(sb, Ah, Wh, bid, 0, tid);
    if (T > 1) issue_stage_g(sb, Ah, Wh, bid, 1, tid);

#pragma unroll 1
    for (int g = 0; g < T; g++) {
        if (g == T - 1) cp_wait<0>(); else cp_wait<1>();
        __syncthreads();                       // one sync per stage
        if (g + 2 < T) issue_stage_g(sb, Ah, Wh, bid, g + 2, tid);

        const uint32_t st = sb + (uint32_t)(g % NSTAGE) * STAGE_B;
        const uint32_t sA = st;
        const uint32_t sB = st + A_TILE_B;

#pragma unroll
        for (int kk = 0; kk < BK / 16; kk++) {
            const int kbase = kk * 16;
            uint32_t a_f[2][4];
#pragma unroll
            for (int mi = 0; mi < 2; mi++) {
                uint32_t ao = (uint32_t)((m_off + mi * 16 + a_row) * PITCH_B
                                         + (kbase + a_kb) * 2);
                ldsm_x4(a_f[mi], sA + ao);
            }
            uint32_t b_f[4][4];
#pragma unroll
            for (int nj = 0; nj < 4; nj++) {
                uint32_t bo = (uint32_t)((n_off + nj * 16 + b_row) * PITCH_B
                                         + (kbase + b_kb) * 2);
                ldsm_x4(b_f[nj], sB + bo);
            }
#pragma unroll
            for (int mi = 0; mi < 2; mi++)
#pragma unroll
                for (int ni = 0; ni < 8; ni++) {
                    const int nj = ni >> 1, q = (ni & 1) * 2;
                    mma_fp16(acc[mi][ni], a_f[mi], b_f[nj][q], b_f[nj][q + 1]);
                }
        }

        if ((g & 7) == 7) {
            // ---- epilogue for tile g/8 (overlaps next tile's loads) ----
            const int tile = bid + (g >> 3) * GPERS;
            const int bn   = (tile % NTILE_N) * 256;
            const int bm   = (tile / NTILE_N) * 128;
            const bool gate = (bn >= HID);
#pragma unroll
            for (int mi = 0; mi < 2; mi++) {
                const int row0 = bm + m_off + mi * 16 + group;
#pragma unroll
                for (int ni = 0; ni < 8; ni++) {
                    const int col = bn + n_off + ni * 8 + tid4 * 2;
                    float u0 = acc[mi][ni][0], u1 = acc[mi][ni][1];
                    float u2 = acc[mi][ni][2], u3 = acc[mi][ni][3];
                    if (gate) {
                        const float bz0 = __ldg(&bias[col - HID]);
                        const float bz1 = __ldg(&bias[col + 1 - HID]);
                        u0 = __fdividef(1.0f, 1.0f + __expf(-(u0 + bz0)));
                        u1 = __fdividef(1.0f, 1.0f + __expf(-(u1 + bz1)));
                        u2 = __fdividef(1.0f, 1.0f + __expf(-(u2 + bz0)));
                        u3 = __fdividef(1.0f, 1.0f + __expf(-(u3 + bz1)));
                    }
                    *reinterpret_cast<__half2*>(&U[(size_t)row0 * NCOLS + col]) =
                        __floats2half2_rn(u0, u1);
                    *reinterpret_cast<__half2*>(&U[(size_t)(row0 + 8) * NCOLS + col]) =
                        __floats2half2_rn(u2, u3);
                    acc[mi][ni][0] = 0.f; acc[mi][ni][1] = 0.f;
                    acc[mi][ni][2] = 0.f; acc[mi][ni][3] = 0.f;
                }
            }
        }
    }
}

// ============================================================
// Chunked parallel scan, half2 lanes, 64 chunks (wide grid).
// ============================================================
__global__ void __launch_bounds__(256)
scan_pass1(const __half* __restrict__ U, float* __restrict__ P, float* __restrict__ S) {
    int gid   = blockIdx.x * blockDim.x + threadIdx.x;   // 0 .. NCH*BH2-1
    int lane2 = gid & (BH2 - 1);
    int kc    = gid >> 12;                               // BH2 = 4096
    int b  = lane2 >> 8;                                 // HID/2 = 256
    int h2 = lane2 & 255;
    int l0 = kc * CHL;
    const __half2* U2 = reinterpret_cast<const __half2*>(U);

    float c0 = 0.f, c1 = 0.f, p0 = 1.f, p1 = 1.f;
    for (int l = l0; l < l0 + CHL; l += SUNROLL) {
        float2 f[SUNROLL], xt[SUNROLL];
#pragma unroll
        for (int u = 0; u < SUNROLL; u++) {
            size_t base = ((size_t)(l + u) * BATCH + b) * (NCOLS / 2) + h2;
            xt[u] = __half22float2(U2[base]);
            f [u] = __half22float2(U2[base + HID / 2]);
        }
#pragma unroll
        for (int u = 0; u < SUNROLL; u++) {
            c0 = fmaf(f[u].x, c0 - xt[u].x, xt[u].x);
            c1 = fmaf(f[u].y, c1 - xt[u].y, xt[u].y);
            p0 *= f[u].x;
            p1 *= f[u].y;
        }
    }
    size_t o2 = (size_t)kc * BH2 + lane2;
    reinterpret_cast<float2*>(P)[o2] = make_float2(p0, p1);
    reinterpret_cast<float2*>(S)[o2] = make_float2(c0, c1);
}

__global__ void __launch_bounds__(256)
scan_pass2(const float* __restrict__ P, const float* __restrict__ S,
           float* __restrict__ Cin) {
    int lane = blockIdx.x * blockDim.x + threadIdx.x;   // 0..BH-1
    float c = 0.f;
#pragma unroll
    for (int k = 0; k < NCH; k++) {
        Cin[(size_t)k * BH + lane] = c;
        c = fmaf(P[(size_t)k * BH + lane], c, S[(size_t)k * BH + lane]);
    }
}

__global__ void __launch_bounds__(256)
scan_pass3(const __half* __restrict__ U, const __half* __restrict__ xin,
           const float* __restrict__ Cin, __half* __restrict__ hout) {
    int gid   = blockIdx.x * blockDim.x + threadIdx.x;
    int lane2 = gid & (BH2 - 1);
    int kc    = gid >> 12;
    int b  = lane2 >> 8;
    int h2 = lane2 & 255;
    int l0 = kc * CHL;
    const __half2* U2 = reinterpret_cast<const __half2*>(U);
    const __half2* X2 = reinterpret_cast<const __half2*>(xin);
    __half2* H2 = reinterpret_cast<__half2*>(hout);

    float2 cin = reinterpret_cast<const float2*>(Cin)[(size_t)kc * BH2 + lane2];
    float c0 = cin.x, c1 = cin.y;
    for (int l = l0; l < l0 + CHL; l += SUNROLL) {
        float2 f[SUNROLL], xt[SUNROLL], r[SUNROLL], xv[SUNROLL];
#pragma unroll
        for (int u = 0; u < SUNROLL; u++) {
            size_t row  = (size_t)(l + u) * BATCH + b;
            size_t base = row * (NCOLS / 2) + h2;
            xt[u] = __half22float2(U2[base]);
            f [u] = __half22float2(U2[base + HID / 2]);
            r [u] = __half22float2(U2[base + HID]);
            xv[u] = __half22float2(X2[row * (HID / 2) + h2]);
        }
#pragma unroll
        for (int u = 0; u < SUNROLL; u++) {
            c0 = fmaf(f[u].x, c0 - xt[u].x, xt[u].x);
            c1 = fmaf(f[u].y, c1 - xt[u].y, xt[u].y);
            float h0 = fmaf(r[u].x, c0 - xv[u].x, xv[u].x);
            float h1 = fmaf(r[u].y, c1 - xv[u].y, xv[u].y);
            size_t row = (size_t)(l + u) * BATCH + b;
            H2[row * (HID / 2) + h2] = __floats2half2_rn(h0, h1);
        }
    }
}

// ============================================================
// Final FC (half2 activation reads, fp32 weights/accum)
// ============================================================
__global__ void __launch_bounds__(256)
fc_kernel(const __half* __restrict__ Hf, const float* __restrict__ fcW,
          const float* __restrict__ fcb, float* __restrict__ out) {
    __shared__ float Wsm[OUT_F * HID];
    int tid = threadIdx.x;
    for (int i = tid; i < OUT_F * HID; i += 256) Wsm[i] = fcW[i];
    __syncthreads();

    int warp = tid >> 5, lane = tid & 31;
    int row = blockIdx.x * 8 + warp;
    const __half2* hp = reinterpret_cast<const __half2*>(Hf + (size_t)row * HID);

    float acc[OUT_F];
#pragma unroll
    for (int n = 0; n < OUT_F; n++) acc[n] = 0.f;

    for (int k2 = lane; k2 < HID / 2; k2 += 32) {
        float2 xv = __half22float2(hp[k2]);
#pragma unroll
        for (int n = 0; n < OUT_F; n++) {
            acc[n] = fmaf(xv.x, Wsm[n * HID + 2 * k2],     acc[n]);
            acc[n] = fmaf(xv.y, Wsm[n * HID + 2 * k2 + 1], acc[n]);
        }
    }
#pragma unroll
    for (int n = 0; n < OUT_F; n++) {
        float v = acc[n];
        v += __shfl_xor_sync(0xFFFFFFFFu, v, 16);
        v += __shfl_xor_sync(0xFFFFFFFFu, v, 8);
        v += __shfl_xor_sync(0xFFFFFFFFu, v, 4);
        v += __shfl_xor_sync(0xFFFFFFFFu, v, 2);
        v += __shfl_xor_sync(0xFFFFFFFFu, v, 1);
        if (lane == 0) out[(size_t)row * OUT_F + n] = v + fcb[n];
    }
}

// ============================================================
// Host launcher (graph-capturable: kernel launches only)
// ============================================================
extern "C" void kernel_launch(void* const* d_in, const int* in_sizes, int n_in,
                              void* d_out, int out_size) {
    const float* x    = (const float*)d_in[0];
    const float* Ws   = (const float*)d_in[1];
    const float* bs   = (const float*)d_in[2];
    const float* fcW  = (const float*)d_in[3];
    const float* fcb  = (const float*)d_in[4];
    float* out        = (float*)d_out;

    float *P, *S, *Cin;
    __half *U, *A0, *A1, *Wh;
    cudaGetSymbolAddress((void**)&U,   g_U);
    cudaGetSymbolAddress((void**)&A0,  g_A0);
    cudaGetSymbolAddress((void**)&A1,  g_A1);
    cudaGetSymbolAddress((void**)&Wh,  g_Wh);
    cudaGetSymbolAddress((void**)&P,   g_P);
    cudaGetSymbolAddress((void**)&S,   g_S);
    cudaGetSymbolAddress((void**)&Cin, g_Cin);

    cudaFuncSetAttribute(sru_gemm_mma,
                         cudaFuncAttributeMaxDynamicSharedMemorySize, SMEM_GEMM);

    const int nA4   = MROWS * HID / 4;
    const int nWall = NLAY * NCOLS * HID / 4;
    const int scan_grid = NCH * BH2 / 256;    // 1024

    // One-time: convert all weights and layer-0 activations to fp16.
    convert_fp16<<<(nWall + 255) / 256, 256>>>(Ws, Wh, nWall);
    convert_fp16<<<(nA4 + 255) / 256, 256>>>(x, A0, nA4);

    __half* cur = A0;
    __half* nxt = A1;
    for (int l = 0; l < NLAY; l++) {
        const size_t woff = (size_t)l * NCOLS * HID;
        sru_gemm_mma<<<GPERS, 512, SMEM_GEMM>>>(cur, Wh + woff,
                                                bs + (size_t)l * (2 * HID), U);
        scan_pass1<<<scan_grid, 256>>>(U, P, S);
        scan_pass2<<<BH / 256, 256>>>(P, S, Cin);
        scan_pass3<<<scan_grid, 256>>>(U, cur, Cin, nxt);
        __half* t = cur; cur = nxt; nxt = t;
    }
    fc_kernel<<<MROWS / 8, 256>>>(cur, fcW, fcb, out);
}